// round 2
// baseline (speedup 1.0000x reference)
#include <cuda_runtime.h>
#include <math.h>

#define BSZ 2
#define HEADS 16
#define SEQ 4096
#define DH 64
#define DM 1024
#define MF 266
#define MP 272          // padded feature dim (pad entries are exact zeros)
#define CHK 128
#define NC 32           // SEQ/CHK
#define BH 32           // BSZ*HEADS
#define TOK (BH*SEQ)    // 131072
#define ROWS (BSZ*SEQ)  // 8192

#define NORMALIZER 0.35355339059327373f   // 64^-0.25
#define DIAG_COEF 0.0625f                 // 0.5 * 64^-0.5
#define RATIO 0.061313933948496584f       // 266^-0.5
#define KEPS 1e-4f
#define CEPS 1e-6f

// ---------------- static scratch (no allocations allowed) ----------------
__device__ float g_lin[(size_t)ROWS*DM];
__device__ float g_q[(size_t)TOK*DH];
__device__ float g_k[(size_t)TOK*DH];
__device__ float g_v[(size_t)TOK*DH];
__device__ float g_qp[(size_t)TOK*MP];
__device__ float g_kp[(size_t)TOK*MP];
__device__ float g_csum[(size_t)BH*NC*MP*DH];
__device__ float g_zsum[(size_t)BH*NC*MP];
__device__ float g_attn[(size_t)ROWS*DM];
__device__ float g_projn[MP*DH];
__device__ unsigned int g_kmax_bits;

// ordered-encode float for atomicMax on unsigned
__device__ __forceinline__ unsigned int enc_f(float f){
    unsigned int u = __float_as_uint(f);
    return (u & 0x80000000u) ? ~u : (u | 0x80000000u);
}
__device__ __forceinline__ float dec_f(unsigned int u){
    return (u & 0x80000000u) ? __uint_as_float(u & 0x7fffffffu)
                             : __uint_as_float(~u);
}

// ---------------- prep: scaled/padded proj + reset global max ----------------
__global__ void prep_kernel(const float* __restrict__ proj){
    int idx = blockIdx.x*256 + threadIdx.x;
    if (idx == 0) g_kmax_bits = 0u;   // below enc(-FLT_MAX)
    if (idx < MP*DH){
        int m = idx / DH, d = idx % DH;
        g_projn[idx] = (m < MF) ? proj[m*DH + d] * NORMALIZER : 0.f;
    }
}

// ---------------- generic SGEMM: C[M,N] = A[M,K] * B[N,K]^T (+bias) --------
// M multiple of 128, K multiple of 16; N guarded.
__global__ __launch_bounds__(256)
void sgemm_nt(int M, int N, int K, const float* __restrict__ A,
              const float* __restrict__ B, float* __restrict__ C,
              int ldc, const float* __restrict__ bias)
{
    __shared__ float As[16][128];
    __shared__ float Bs[16][128];
    const int m0 = blockIdx.y * 128;
    const int n0 = blockIdx.x * 128;
    const int tid = threadIdx.x;
    const int tx = tid & 15;
    const int ty = tid >> 4;
    const int lr = tid >> 2;        // 0..63
    const int lc = (tid & 3) << 2;  // 0,4,8,12

    float acc[8][8];
    #pragma unroll
    for (int i=0;i<8;i++)
        #pragma unroll
        for (int j=0;j<8;j++) acc[i][j]=0.f;

    for (int k0 = 0; k0 < K; k0 += 16){
        #pragma unroll
        for (int s = 0; s < 2; s++){
            int row = lr + s*64;
            float4 a = *(const float4*)(A + (size_t)(m0+row)*K + k0 + lc);
            As[lc+0][row]=a.x; As[lc+1][row]=a.y; As[lc+2][row]=a.z; As[lc+3][row]=a.w;
            float4 b = make_float4(0.f,0.f,0.f,0.f);
            if (n0 + row < N)
                b = *(const float4*)(B + (size_t)(n0+row)*K + k0 + lc);
            Bs[lc+0][row]=b.x; Bs[lc+1][row]=b.y; Bs[lc+2][row]=b.z; Bs[lc+3][row]=b.w;
        }
        __syncthreads();
        #pragma unroll
        for (int kk = 0; kk < 16; kk++){
            float af[8], bf[8];
            *(float4*)&af[0] = *(const float4*)&As[kk][ty*8];
            *(float4*)&af[4] = *(const float4*)&As[kk][ty*8+4];
            *(float4*)&bf[0] = *(const float4*)&Bs[kk][tx*8];
            *(float4*)&bf[4] = *(const float4*)&Bs[kk][tx*8+4];
            #pragma unroll
            for (int i=0;i<8;i++)
                #pragma unroll
                for (int j=0;j<8;j++)
                    acc[i][j] = fmaf(af[i], bf[j], acc[i][j]);
        }
        __syncthreads();
    }
    #pragma unroll
    for (int i=0;i<8;i++){
        int row = m0 + ty*8 + i;
        #pragma unroll
        for (int j=0;j<8;j++){
            int col = n0 + tx*8 + j;
            if (col < N){
                float v = acc[i][j];
                if (bias) v += bias[col];
                C[(size_t)row*ldc + col] = v;
            }
        }
    }
}

// ---------------- split heads: [b,n,1024]+bias -> [bh,n,64] -----------------
__global__ void split_heads(const float* __restrict__ lin,
                            const float* __restrict__ bias,
                            float* __restrict__ dst)
{
    int idx = blockIdx.x*256 + threadIdx.x;       // over ROWS*DM
    int r = idx >> 10;
    int c = idx & 1023;
    int b = r >> 12, n = r & 4095;
    int h = c >> 6,  d = c & 63;
    dst[(((size_t)(b*HEADS + h))*SEQ + n)*DH + d] = lin[idx] + bias[c];
}

// ---------------- global max over k's data_dash ----------------------------
__global__ void kmax_kernel(const float* __restrict__ kp_)
{
    __shared__ float smx[8];
    int warp = threadIdx.x >> 5, lane = threadIdx.x & 31;
    size_t row = (size_t)blockIdx.x*8 + warp;
    const float* dd = kp_ + row*MP;
    float mx = -3.4e38f;
    #pragma unroll
    for (int i=0;i<9;i++){
        int m = i*32 + lane;
        if (m < MF) mx = fmaxf(mx, dd[m]);
    }
    #pragma unroll
    for (int o=16;o;o>>=1) mx = fmaxf(mx, __shfl_xor_sync(0xffffffffu, mx, o));
    if (lane==0) smx[warp]=mx;
    __syncthreads();
    if (threadIdx.x==0){
        float m = smx[0];
        #pragma unroll
        for (int w=1;w<8;w++) m = fmaxf(m, smx[w]);
        atomicMax(&g_kmax_bits, enc_f(m));
    }
}

// ---------------- apply exp feature map in-place ----------------------------
__global__ void feat_apply(const float* __restrict__ data,
                           float* __restrict__ ddb, int is_query)
{
    int warp = threadIdx.x >> 5, lane = threadIdx.x & 31;
    size_t row = (size_t)blockIdx.x*8 + warp;
    float2 qq = ((const float2*)(data + row*DH))[lane];
    float s = qq.x*qq.x + qq.y*qq.y;
    #pragma unroll
    for (int o=16;o;o>>=1) s += __shfl_xor_sync(0xffffffffu, s, o);
    float diag = DIAG_COEF * s;

    float* dd = ddb + row*MP;
    float vals[9];
    float mx;
    if (is_query){
        mx = -3.4e38f;
        #pragma unroll
        for (int i=0;i<9;i++){
            int m = i*32 + lane;
            float v = (m < MP) ? dd[m] : 0.f;
            vals[i] = v;
            if (m < MF) mx = fmaxf(mx, v);
        }
        #pragma unroll
        for (int o=16;o;o>>=1) mx = fmaxf(mx, __shfl_xor_sync(0xffffffffu, mx, o));
    } else {
        #pragma unroll
        for (int i=0;i<9;i++){
            int m = i*32 + lane;
            vals[i] = (m < MP) ? dd[m] : 0.f;
        }
        mx = dec_f(g_kmax_bits);
    }
    #pragma unroll
    for (int i=0;i<9;i++){
        int m = i*32 + lane;
        if (m < MP)
            dd[m] = (m < MF) ? RATIO*(expf(vals[i]-diag-mx)+KEPS) : 0.f;
    }
}

// ---------------- per-chunk Csum = K'^T V, zsum = colsum(K') ----------------
extern __shared__ float s_dyn[];
__global__ __launch_bounds__(256)
void chunk_sums()
{
    float* Ks = s_dyn;               // [128][272]
    float* Vs = s_dyn + CHK*MP;      // [128][64]
    int blk = blockIdx.x;            // bh*NC + c ; token0 = blk*128
    size_t tok0 = (size_t)blk * CHK;
    int tid = threadIdx.x;

    const float4* ksrc = (const float4*)(g_kp + tok0*MP);
    float4* kdst = (float4*)Ks;
    #pragma unroll
    for (int j=0;j<34;j++) kdst[j*256 + tid] = ksrc[j*256 + tid];
    const float4* vsrc = (const float4*)(g_v + tok0*DH);
    float4* vdst = (float4*)Vs;
    #pragma unroll
    for (int j=0;j<8;j++) vdst[j*256 + tid] = vsrc[j*256 + tid];
    __syncthreads();

    int d2 = tid & 31;     // float2 index over 64 d
    int mg = tid >> 5;     // 0..7
    float2 acc[34];
    #pragma unroll
    for (int i=0;i<34;i++){ acc[i].x=0.f; acc[i].y=0.f; }
    const float2* V2 = (const float2*)Vs;
    for (int t=0;t<CHK;t++){
        float2 v = V2[t*32 + d2];
        const float* kr = Ks + t*MP + mg*34;
        #pragma unroll
        for (int mi=0;mi<34;mi++){
            float kk = kr[mi];
            acc[mi].x = fmaf(kk, v.x, acc[mi].x);
            acc[mi].y = fmaf(kk, v.y, acc[mi].y);
        }
    }
    float* cdst = g_csum + (size_t)blk*MP*DH;
    #pragma unroll
    for (int mi=0;mi<34;mi++){
        int m = mg*34 + mi;
        ((float2*)(cdst + (size_t)m*DH))[d2] = acc[mi];
    }
    for (int m = tid; m < MP; m += 256){
        float sm = 0.f;
        for (int t=0;t<CHK;t++) sm += Ks[t*MP + m];
        g_zsum[(size_t)blk*MP + m] = sm;
    }
}

// ---------------- exclusive scan over chunks (in place) ---------------------
__global__ __launch_bounds__(256)
void scan_chunks()
{
    int bh = blockIdx.x, tid = threadIdx.x;
    float2 st[34];
    #pragma unroll
    for (int i=0;i<34;i++){ st[i].x=0.f; st[i].y=0.f; }
    float2 zst; zst.x=0.f; zst.y=0.f;
    bool zact = tid < 136;
    for (int c=0;c<NC;c++){
        float2* p = (float2*)(g_csum + ((size_t)bh*NC + c)*MP*DH);
        #pragma unroll
        for (int i=0;i<34;i++){
            int j = i*256 + tid;
            float2 t = p[j];
            p[j] = st[i];
            st[i].x += t.x; st[i].y += t.y;
        }
        if (zact){
            float2* zp = (float2*)(g_zsum + ((size_t)bh*NC + c)*MP);
            float2 t = zp[tid];
            zp[tid] = zst;
            zst.x += t.x; zst.y += t.y;
        }
    }
}

// ---------------- per-chunk output: O = Q'S_prev + tril(Q'K'^T)V ------------
__global__ __launch_bounds__(256,1)
void out_chunk()
{
    float* Qs  = s_dyn;                      // [16][128]
    float* KsT = s_dyn + 16*128;             // [16][128]
    float* Ss  = s_dyn + 2*16*128;           // [16][64]
    float* zs  = s_dyn + 2*16*128 + 16*64;   // [16]
    float* Am  = s_dyn;                      // [128][129]  (reuses stage-A area)
    float* Vs  = s_dyn + 128*129;            // [128][64]

    int blk = blockIdx.x;
    int bh = blk >> 5, c = blk & 31;
    size_t tok0 = (size_t)blk * CHK;
    int tid = threadIdx.x;
    int tx = tid & 15, ty = tid >> 4;
    int lr = tid >> 2;        // 0..63
    int lc4 = tid & 3;

    { // V load: region disjoint from stage-A tiles
        const float4* vsrc = (const float4*)(g_v + tok0*DH);
        float4* vdst = (float4*)Vs;
        #pragma unroll
        for (int j=0;j<8;j++) vdst[j*256 + tid] = vsrc[j*256 + tid];
    }

    float accA[8][8], accO[8][4], accD[8], accQ[8];
    #pragma unroll
    for (int i=0;i<8;i++){
        accD[i]=0.f; accQ[i]=0.f;
        #pragma unroll
        for (int j=0;j<8;j++) accA[i][j]=0.f;
        #pragma unroll
        for (int d=0;d<4;d++) accO[i][d]=0.f;
    }

    const float* Sprev = g_csum + (size_t)blk*MP*DH;
    const float* zprev = g_zsum + (size_t)blk*MP;

    for (int mt = 0; mt < MP; mt += 16){
        __syncthreads();
        #pragma unroll
        for (int s = 0; s < 2; s++){
            int row = lr + s*64;
            float4 a = *(const float4*)(g_qp + (tok0+row)*MP + mt + lc4*4);
            Qs[(lc4*4+0)*128+row]=a.x; Qs[(lc4*4+1)*128+row]=a.y;
            Qs[(lc4*4+2)*128+row]=a.z; Qs[(lc4*4+3)*128+row]=a.w;
            float4 b = *(const float4*)(g_kp + (tok0+row)*MP + mt + lc4*4);
            KsT[(lc4*4+0)*128+row]=b.x; KsT[(lc4*4+1)*128+row]=b.y;
            KsT[(lc4*4+2)*128+row]=b.z; KsT[(lc4*4+3)*128+row]=b.w;
        }
        {
            int sr = tid >> 4, sc = tid & 15;
            float4 sv = *(const float4*)(Sprev + (size_t)(mt+sr)*DH + sc*4);
            *(float4*)&Ss[sr*64 + sc*4] = sv;
        }
        if (tid < 16) zs[tid] = zprev[mt + tid];
        __syncthreads();
        #pragma unroll
        for (int mk=0;mk<16;mk++){
            float af[8], bf[8], sf[4];
            *(float4*)&af[0] = *(const float4*)&Qs[mk*128 + ty*8];
            *(float4*)&af[4] = *(const float4*)&Qs[mk*128 + ty*8+4];
            *(float4*)&bf[0] = *(const float4*)&KsT[mk*128 + tx*8];
            *(float4*)&bf[4] = *(const float4*)&KsT[mk*128 + tx*8+4];
            *(float4*)&sf[0] = *(const float4*)&Ss[mk*64 + tx*4];
            float zv = zs[mk];
            #pragma unroll
            for (int i=0;i<8;i++){
                #pragma unroll
                for (int j=0;j<8;j++) accA[i][j] = fmaf(af[i], bf[j], accA[i][j]);
                #pragma unroll
                for (int d=0;d<4;d++)  accO[i][d] = fmaf(af[i], sf[d], accO[i][d]);
                accD[i] = fmaf(af[i], zv, accD[i]);
                accQ[i] += af[i];
            }
        }
    }
    __syncthreads();
    #pragma unroll
    for (int i=0;i<8;i++)
        #pragma unroll
        for (int j=0;j<8;j++)
            Am[(ty*8+i)*129 + tx*8 + j] = accA[i][j];
    __syncthreads();

    for (int j=0;j<CHK;j++){
        float4 v = *(const float4*)&Vs[j*64 + tx*4];
        #pragma unroll
        for (int i=0;i<8;i++){
            int row = ty*8 + i;
            float a = (j <= row) ? Am[row*129 + j] : 0.f;
            accO[i][0] = fmaf(a, v.x, accO[i][0]);
            accO[i][1] = fmaf(a, v.y, accO[i][1]);
            accO[i][2] = fmaf(a, v.z, accO[i][2]);
            accO[i][3] = fmaf(a, v.w, accO[i][3]);
            accD[i] += a;
        }
    }

    int b = bh >> 4, h = bh & 15;
    #pragma unroll
    for (int i=0;i<8;i++){
        int r = ty*8 + i;
        int n = c*CHK + r;
        float inv = 1.f / (accD[i] + CEPS*accQ[i]);
        float4 o;
        o.x = accO[i][0]*inv; o.y = accO[i][1]*inv;
        o.z = accO[i][2]*inv; o.w = accO[i][3]*inv;
        *(float4*)(g_attn + ((size_t)(b*SEQ + n))*DM + h*DH + tx*4) = o;
    }
}

// ---------------- launch ----------------------------------------------------
extern "C" void kernel_launch(void* const* d_in, const int* in_sizes, int n_in,
                              void* d_out, int out_size)
{
    (void)in_sizes; (void)n_in; (void)out_size;
    const float* x    = (const float*)d_in[0];
    const float* Wq   = (const float*)d_in[1];
    const float* bq   = (const float*)d_in[2];
    const float* Wk   = (const float*)d_in[3];
    const float* bk   = (const float*)d_in[4];
    const float* Wv   = (const float*)d_in[5];
    const float* bv   = (const float*)d_in[6];
    const float* Wo   = (const float*)d_in[7];
    const float* bo   = (const float*)d_in[8];
    const float* proj = (const float*)d_in[9];
    float* out = (float*)d_out;

    cudaFuncSetAttribute(chunk_sums, cudaFuncAttributeMaxDynamicSharedMemorySize,
                         (CHK*MP + CHK*DH)*4);
    cudaFuncSetAttribute(out_chunk, cudaFuncAttributeMaxDynamicSharedMemorySize,
                         (128*129 + 128*64)*4);

    float *lin,*q,*k,*v,*qp,*kp,*attn,*projn;
    cudaGetSymbolAddress((void**)&lin,   g_lin);
    cudaGetSymbolAddress((void**)&q,     g_q);
    cudaGetSymbolAddress((void**)&k,     g_k);
    cudaGetSymbolAddress((void**)&v,     g_v);
    cudaGetSymbolAddress((void**)&qp,    g_qp);
    cudaGetSymbolAddress((void**)&kp,    g_kp);
    cudaGetSymbolAddress((void**)&attn,  g_attn);
    cudaGetSymbolAddress((void**)&projn, g_projn);

    prep_kernel<<<(MP*DH+255)/256, 256>>>(proj);

    dim3 gqkv(DM/128, ROWS/128);   // (8, 64)
    sgemm_nt<<<gqkv,256>>>(ROWS, DM, DM, x, Wq, lin, DM, nullptr);
    split_heads<<<ROWS*DM/256,256>>>(lin, bq, q);
    sgemm_nt<<<gqkv,256>>>(ROWS, DM, DM, x, Wk, lin, DM, nullptr);
    split_heads<<<ROWS*DM/256,256>>>(lin, bk, k);
    sgemm_nt<<<gqkv,256>>>(ROWS, DM, DM, x, Wv, lin, DM, nullptr);
    split_heads<<<ROWS*DM/256,256>>>(lin, bv, v);

    dim3 gdd((MP+127)/128, TOK/128);  // (3, 1024)
    sgemm_nt<<<gdd,256>>>(TOK, MP, DH, q, projn, qp, MP, nullptr);
    sgemm_nt<<<gdd,256>>>(TOK, MP, DH, k, projn, kp, MP, nullptr);

    feat_apply<<<TOK/8,256>>>(q, qp, 1);
    kmax_kernel<<<TOK/8,256>>>(kp);
    feat_apply<<<TOK/8,256>>>(k, kp, 0);

    chunk_sums<<<BH*NC,256,(CHK*MP + CHK*DH)*4>>>();
    scan_chunks<<<BH,256>>>();
    out_chunk<<<BH*NC,256,(128*129 + 128*64)*4>>>();

    sgemm_nt<<<gqkv,256>>>(ROWS, DM, DM, attn, Wo, out, DM, bo);
}

// round 3
// speedup vs baseline: 1.6579x; 1.6579x over previous
#include <cuda_runtime.h>
#include <math.h>

#define BSZ 2
#define HEADS 16
#define SEQ 4096
#define DH 64
#define DM 1024
#define MF 266
#define MP 272          // padded feature dim (pad entries are exact zeros)
#define CHK 128
#define NC 32           // SEQ/CHK
#define BH 32           // BSZ*HEADS
#define TOK (BH*SEQ)    // 131072
#define ROWS (BSZ*SEQ)  // 8192

#define NORMALIZER 0.35355339059327373f   // 64^-0.25
#define DIAG_COEF 0.0625f                 // 0.5 * 64^-0.5
#define RATIO 0.061313933948496584f       // 266^-0.5
#define KEPS 1e-4f
#define CEPS 1e-6f

// ---------------- static scratch (no allocations allowed) ----------------
__device__ float g_lin[(size_t)ROWS*DM];
__device__ float g_q[(size_t)TOK*DH];
__device__ float g_k[(size_t)TOK*DH];
__device__ float g_v[(size_t)TOK*DH];
__device__ float g_qp[(size_t)TOK*MP];
__device__ float g_kp[(size_t)TOK*MP];
__device__ float g_csum[(size_t)BH*NC*MP*DH];
__device__ float g_zsum[(size_t)BH*NC*MP];
__device__ float g_attn[(size_t)ROWS*DM];
__device__ float g_projn[MP*DH];
__device__ unsigned int g_kmax_bits;

// ordered-encode float for atomicMax on unsigned
__device__ __forceinline__ unsigned int enc_f(float f){
    unsigned int u = __float_as_uint(f);
    return (u & 0x80000000u) ? ~u : (u | 0x80000000u);
}
__device__ __forceinline__ float dec_f(unsigned int u){
    return (u & 0x80000000u) ? __uint_as_float(u & 0x7fffffffu)
                             : __uint_as_float(~u);
}

__device__ __forceinline__ unsigned int f2tf32(float f){
    unsigned int r;
    asm("cvt.rna.tf32.f32 %0, %1;" : "=r"(r) : "f"(f));
    return r;
}

// ---------------- prep: scaled/padded proj + reset global max ----------------
__global__ void prep_kernel(const float* __restrict__ proj){
    int idx = blockIdx.x*256 + threadIdx.x;
    if (idx == 0) g_kmax_bits = 0u;   // below enc(-FLT_MAX)
    if (idx < MP*DH){
        int m = idx / DH, d = idx % DH;
        g_projn[idx] = (m < MF) ? proj[m*DH + d] * NORMALIZER : 0.f;
    }
}

// ---------------- tf32 tensor-core GEMM: C[M,N] = A[M,K] * B[N,K]^T (+bias) --
// 128x128 CTA tile, k-step 16, 8 warps each 64x32 (4x4 m16n8k8 frags).
// M multiple of 128, K multiple of 16; N guarded.
__global__ __launch_bounds__(256)
void sgemm_tf32(int M, int N, int K, const float* __restrict__ A,
                const float* __restrict__ B, float* __restrict__ C,
                int ldc, const float* __restrict__ bias)
{
    __shared__ unsigned int As[16*136];
    __shared__ unsigned int Bs[16*136];
    const int m0 = blockIdx.y * 128;
    const int n0 = blockIdx.x * 128;
    const int tid = threadIdx.x;
    const int lane = tid & 31;
    const int wid  = tid >> 5;
    const int wm = (wid & 1) * 64;
    const int wn = (wid >> 1) * 32;
    const int lr = tid >> 2;        // 0..63 (global-load row)
    const int lc = (tid & 3) << 2;  // 0,4,8,12 (global-load k offset)
    const int qr = lane >> 2;       // 0..7
    const int qc = lane & 3;        // 0..3

    float acc[4][4][4];
    #pragma unroll
    for (int i=0;i<4;i++)
        #pragma unroll
        for (int j=0;j<4;j++)
            #pragma unroll
            for (int c=0;c<4;c++) acc[i][j][c]=0.f;

    // prefetch tile k0=0
    float4 pa[2], pb[2];
    #pragma unroll
    for (int s=0;s<2;s++){
        int row = lr + s*64;
        pa[s] = *(const float4*)(A + (size_t)(m0+row)*K + lc);
        pb[s] = make_float4(0.f,0.f,0.f,0.f);
        if (n0 + row < N)
            pb[s] = *(const float4*)(B + (size_t)(n0+row)*K + lc);
    }

    for (int k0 = 0; k0 < K; k0 += 16){
        // store prefetched tile (convert to tf32)
        #pragma unroll
        for (int s=0;s<2;s++){
            int row = lr + s*64;
            As[(lc+0)*136+row]=f2tf32(pa[s].x); As[(lc+1)*136+row]=f2tf32(pa[s].y);
            As[(lc+2)*136+row]=f2tf32(pa[s].z); As[(lc+3)*136+row]=f2tf32(pa[s].w);
            Bs[(lc+0)*136+row]=f2tf32(pb[s].x); Bs[(lc+1)*136+row]=f2tf32(pb[s].y);
            Bs[(lc+2)*136+row]=f2tf32(pb[s].z); Bs[(lc+3)*136+row]=f2tf32(pb[s].w);
        }
        __syncthreads();

        // prefetch next tile
        if (k0 + 16 < K){
            #pragma unroll
            for (int s=0;s<2;s++){
                int row = lr + s*64;
                pa[s] = *(const float4*)(A + (size_t)(m0+row)*K + k0+16 + lc);
                pb[s] = make_float4(0.f,0.f,0.f,0.f);
                if (n0 + row < N)
                    pb[s] = *(const float4*)(B + (size_t)(n0+row)*K + k0+16 + lc);
            }
        }

        #pragma unroll
        for (int k8=0;k8<2;k8++){
            unsigned int af[4][4];
            #pragma unroll
            for (int mf=0;mf<4;mf++){
                int r0 = wm + mf*16 + qr;
                af[mf][0] = As[(qc   + k8*8)*136 + r0];
                af[mf][1] = As[(qc   + k8*8)*136 + r0 + 8];
                af[mf][2] = As[(qc+4 + k8*8)*136 + r0];
                af[mf][3] = As[(qc+4 + k8*8)*136 + r0 + 8];
            }
            unsigned int bf[4][2];
            #pragma unroll
            for (int nf=0;nf<4;nf++){
                int cn = wn + nf*8 + qr;
                bf[nf][0] = Bs[(qc   + k8*8)*136 + cn];
                bf[nf][1] = Bs[(qc+4 + k8*8)*136 + cn];
            }
            #pragma unroll
            for (int mf=0;mf<4;mf++)
                #pragma unroll
                for (int nf=0;nf<4;nf++){
                    asm volatile(
                      "mma.sync.aligned.m16n8k8.row.col.f32.tf32.tf32.f32 "
                      "{%0,%1,%2,%3}, {%4,%5,%6,%7}, {%8,%9}, {%0,%1,%2,%3};"
                      : "+f"(acc[mf][nf][0]), "+f"(acc[mf][nf][1]),
                        "+f"(acc[mf][nf][2]), "+f"(acc[mf][nf][3])
                      : "r"(af[mf][0]), "r"(af[mf][1]),
                        "r"(af[mf][2]), "r"(af[mf][3]),
                        "r"(bf[nf][0]), "r"(bf[nf][1]));
                }
        }
        __syncthreads();
    }

    #pragma unroll
    for (int mf=0;mf<4;mf++){
        #pragma unroll
        for (int nf=0;nf<4;nf++){
            int row = m0 + wm + mf*16 + qr;
            int col = n0 + wn + nf*8 + qc*2;
            if (col < N){
                float b0 = bias ? bias[col]   : 0.f;
                float b1 = bias ? bias[col+1] : 0.f;
                float2 v0; v0.x = acc[mf][nf][0]+b0; v0.y = acc[mf][nf][1]+b1;
                float2 v1; v1.x = acc[mf][nf][2]+b0; v1.y = acc[mf][nf][3]+b1;
                *(float2*)(C + (size_t)row*ldc + col)     = v0;
                *(float2*)(C + (size_t)(row+8)*ldc + col) = v1;
            }
        }
    }
}

// ---------------- split heads: [b,n,1024]+bias -> [bh,n,64] -----------------
__global__ void split_heads(const float* __restrict__ lin,
                            const float* __restrict__ bias,
                            float* __restrict__ dst)
{
    int idx = blockIdx.x*256 + threadIdx.x;       // over ROWS*DM
    int r = idx >> 10;
    int c = idx & 1023;
    int b = r >> 12, n = r & 4095;
    int h = c >> 6,  d = c & 63;
    dst[(((size_t)(b*HEADS + h))*SEQ + n)*DH + d] = lin[idx] + bias[c];
}

// ---------------- global max over k's data_dash ----------------------------
__global__ void kmax_kernel(const float* __restrict__ kp_)
{
    __shared__ float smx[8];
    int warp = threadIdx.x >> 5, lane = threadIdx.x & 31;
    size_t row = (size_t)blockIdx.x*8 + warp;
    const float* dd = kp_ + row*MP;
    float mx = -3.4e38f;
    #pragma unroll
    for (int i=0;i<9;i++){
        int m = i*32 + lane;
        if (m < MF) mx = fmaxf(mx, dd[m]);
    }
    #pragma unroll
    for (int o=16;o;o>>=1) mx = fmaxf(mx, __shfl_xor_sync(0xffffffffu, mx, o));
    if (lane==0) smx[warp]=mx;
    __syncthreads();
    if (threadIdx.x==0){
        float m = smx[0];
        #pragma unroll
        for (int w=1;w<8;w++) m = fmaxf(m, smx[w]);
        atomicMax(&g_kmax_bits, enc_f(m));
    }
}

// ---------------- apply exp feature map in-place ----------------------------
__global__ void feat_apply(const float* __restrict__ data,
                           float* __restrict__ ddb, int is_query)
{
    int warp = threadIdx.x >> 5, lane = threadIdx.x & 31;
    size_t row = (size_t)blockIdx.x*8 + warp;
    float2 qq = ((const float2*)(data + row*DH))[lane];
    float s = qq.x*qq.x + qq.y*qq.y;
    #pragma unroll
    for (int o=16;o;o>>=1) s += __shfl_xor_sync(0xffffffffu, s, o);
    float diag = DIAG_COEF * s;

    float* dd = ddb + row*MP;
    float vals[9];
    float mx;
    if (is_query){
        mx = -3.4e38f;
        #pragma unroll
        for (int i=0;i<9;i++){
            int m = i*32 + lane;
            float v = (m < MP) ? dd[m] : 0.f;
            vals[i] = v;
            if (m < MF) mx = fmaxf(mx, v);
        }
        #pragma unroll
        for (int o=16;o;o>>=1) mx = fmaxf(mx, __shfl_xor_sync(0xffffffffu, mx, o));
    } else {
        #pragma unroll
        for (int i=0;i<9;i++){
            int m = i*32 + lane;
            vals[i] = (m < MP) ? dd[m] : 0.f;
        }
        mx = dec_f(g_kmax_bits);
    }
    #pragma unroll
    for (int i=0;i<9;i++){
        int m = i*32 + lane;
        if (m < MP)
            dd[m] = (m < MF) ? RATIO*(expf(vals[i]-diag-mx)+KEPS) : 0.f;
    }
}

// ---------------- per-chunk Csum = K'^T V, zsum = colsum(K') ----------------
extern __shared__ float s_dyn[];
__global__ __launch_bounds__(256)
void chunk_sums()
{
    float* Ks = s_dyn;               // [128][272]
    float* Vs = s_dyn + CHK*MP;      // [128][64]
    int blk = blockIdx.x;            // bh*NC + c ; token0 = blk*128
    size_t tok0 = (size_t)blk * CHK;
    int tid = threadIdx.x;

    const float4* ksrc = (const float4*)(g_kp + tok0*MP);
    float4* kdst = (float4*)Ks;
    #pragma unroll
    for (int j=0;j<34;j++) kdst[j*256 + tid] = ksrc[j*256 + tid];
    const float4* vsrc = (const float4*)(g_v + tok0*DH);
    float4* vdst = (float4*)Vs;
    #pragma unroll
    for (int j=0;j<8;j++) vdst[j*256 + tid] = vsrc[j*256 + tid];
    __syncthreads();

    int d2 = tid & 31;     // float2 index over 64 d
    int mg = tid >> 5;     // 0..7
    float2 acc[34];
    #pragma unroll
    for (int i=0;i<34;i++){ acc[i].x=0.f; acc[i].y=0.f; }
    const float2* V2 = (const float2*)Vs;
    for (int t=0;t<CHK;t++){
        float2 v = V2[t*32 + d2];
        const float* kr = Ks + t*MP + mg*34;
        #pragma unroll
        for (int mi=0;mi<34;mi++){
            float kk = kr[mi];
            acc[mi].x = fmaf(kk, v.x, acc[mi].x);
            acc[mi].y = fmaf(kk, v.y, acc[mi].y);
        }
    }
    float* cdst = g_csum + (size_t)blk*MP*DH;
    #pragma unroll
    for (int mi=0;mi<34;mi++){
        int m = mg*34 + mi;
        ((float2*)(cdst + (size_t)m*DH))[d2] = acc[mi];
    }
    for (int m = tid; m < MP; m += 256){
        float sm = 0.f;
        for (int t=0;t<CHK;t++) sm += Ks[t*MP + m];
        g_zsum[(size_t)blk*MP + m] = sm;
    }
}

// ---------------- exclusive scan over chunks (in place) ---------------------
__global__ __launch_bounds__(256)
void scan_chunks()
{
    int bh = blockIdx.x, tid = threadIdx.x;
    float2 st[34];
    #pragma unroll
    for (int i=0;i<34;i++){ st[i].x=0.f; st[i].y=0.f; }
    float2 zst; zst.x=0.f; zst.y=0.f;
    bool zact = tid < 136;
    for (int c=0;c<NC;c++){
        float2* p = (float2*)(g_csum + ((size_t)bh*NC + c)*MP*DH);
        #pragma unroll
        for (int i=0;i<34;i++){
            int j = i*256 + tid;
            float2 t = p[j];
            p[j] = st[i];
            st[i].x += t.x; st[i].y += t.y;
        }
        if (zact){
            float2* zp = (float2*)(g_zsum + ((size_t)bh*NC + c)*MP);
            float2 t = zp[tid];
            zp[tid] = zst;
            zst.x += t.x; zst.y += t.y;
        }
    }
}

// ---------------- per-chunk output: O = Q'S_prev + tril(Q'K'^T)V ------------
__global__ __launch_bounds__(256,1)
void out_chunk()
{
    float* Qs  = s_dyn;                      // [16][128]
    float* KsT = s_dyn + 16*128;             // [16][128]
    float* Ss  = s_dyn + 2*16*128;           // [16][64]
    float* zs  = s_dyn + 2*16*128 + 16*64;   // [16]
    float* Am  = s_dyn;                      // [128][129]  (reuses stage-A area)
    float* Vs  = s_dyn + 128*129;            // [128][64]

    int blk = blockIdx.x;
    int bh = blk >> 5, c = blk & 31;
    size_t tok0 = (size_t)blk * CHK;
    int tid = threadIdx.x;
    int tx = tid & 15, ty = tid >> 4;
    int lr = tid >> 2;        // 0..63
    int lc4 = tid & 3;

    { // V load: region disjoint from stage-A tiles
        const float4* vsrc = (const float4*)(g_v + tok0*DH);
        float4* vdst = (float4*)Vs;
        #pragma unroll
        for (int j=0;j<8;j++) vdst[j*256 + tid] = vsrc[j*256 + tid];
    }

    float accA[8][8], accO[8][4], accD[8], accQ[8];
    #pragma unroll
    for (int i=0;i<8;i++){
        accD[i]=0.f; accQ[i]=0.f;
        #pragma unroll
        for (int j=0;j<8;j++) accA[i][j]=0.f;
        #pragma unroll
        for (int d=0;d<4;d++) accO[i][d]=0.f;
    }

    const float* Sprev = g_csum + (size_t)blk*MP*DH;
    const float* zprev = g_zsum + (size_t)blk*MP;

    for (int mt = 0; mt < MP; mt += 16){
        __syncthreads();
        #pragma unroll
        for (int s = 0; s < 2; s++){
            int row = lr + s*64;
            float4 a = *(const float4*)(g_qp + (tok0+row)*MP + mt + lc4*4);
            Qs[(lc4*4+0)*128+row]=a.x; Qs[(lc4*4+1)*128+row]=a.y;
            Qs[(lc4*4+2)*128+row]=a.z; Qs[(lc4*4+3)*128+row]=a.w;
            float4 b = *(const float4*)(g_kp + (tok0+row)*MP + mt + lc4*4);
            KsT[(lc4*4+0)*128+row]=b.x; KsT[(lc4*4+1)*128+row]=b.y;
            KsT[(lc4*4+2)*128+row]=b.z; KsT[(lc4*4+3)*128+row]=b.w;
        }
        {
            int sr = tid >> 4, sc = tid & 15;
            float4 sv = *(const float4*)(Sprev + (size_t)(mt+sr)*DH + sc*4);
            *(float4*)&Ss[sr*64 + sc*4] = sv;
        }
        if (tid < 16) zs[tid] = zprev[mt + tid];
        __syncthreads();
        #pragma unroll
        for (int mk=0;mk<16;mk++){
            float af[8], bf[8], sf[4];
            *(float4*)&af[0] = *(const float4*)&Qs[mk*128 + ty*8];
            *(float4*)&af[4] = *(const float4*)&Qs[mk*128 + ty*8+4];
            *(float4*)&bf[0] = *(const float4*)&KsT[mk*128 + tx*8];
            *(float4*)&bf[4] = *(const float4*)&KsT[mk*128 + tx*8+4];
            *(float4*)&sf[0] = *(const float4*)&Ss[mk*64 + tx*4];
            float zv = zs[mk];
            #pragma unroll
            for (int i=0;i<8;i++){
                #pragma unroll
                for (int j=0;j<8;j++) accA[i][j] = fmaf(af[i], bf[j], accA[i][j]);
                #pragma unroll
                for (int d=0;d<4;d++)  accO[i][d] = fmaf(af[i], sf[d], accO[i][d]);
                accD[i] = fmaf(af[i], zv, accD[i]);
                accQ[i] += af[i];
            }
        }
    }
    __syncthreads();
    #pragma unroll
    for (int i=0;i<8;i++)
        #pragma unroll
        for (int j=0;j<8;j++)
            Am[(ty*8+i)*129 + tx*8 + j] = accA[i][j];
    __syncthreads();

    for (int j=0;j<CHK;j++){
        float4 v = *(const float4*)&Vs[j*64 + tx*4];
        #pragma unroll
        for (int i=0;i<8;i++){
            int row = ty*8 + i;
            float a = (j <= row) ? Am[row*129 + j] : 0.f;
            accO[i][0] = fmaf(a, v.x, accO[i][0]);
            accO[i][1] = fmaf(a, v.y, accO[i][1]);
            accO[i][2] = fmaf(a, v.z, accO[i][2]);
            accO[i][3] = fmaf(a, v.w, accO[i][3]);
            accD[i] += a;
        }
    }

    int b = bh >> 4, h = bh & 15;
    #pragma unroll
    for (int i=0;i<8;i++){
        int r = ty*8 + i;
        int n = c*CHK + r;
        float inv = 1.f / (accD[i] + CEPS*accQ[i]);
        float4 o;
        o.x = accO[i][0]*inv; o.y = accO[i][1]*inv;
        o.z = accO[i][2]*inv; o.w = accO[i][3]*inv;
        *(float4*)(g_attn + ((size_t)(b*SEQ + n))*DM + h*DH + tx*4) = o;
    }
}

// ---------------- launch ----------------------------------------------------
extern "C" void kernel_launch(void* const* d_in, const int* in_sizes, int n_in,
                              void* d_out, int out_size)
{
    (void)in_sizes; (void)n_in; (void)out_size;
    const float* x    = (const float*)d_in[0];
    const float* Wq   = (const float*)d_in[1];
    const float* bq   = (const float*)d_in[2];
    const float* Wk   = (const float*)d_in[3];
    const float* bk   = (const float*)d_in[4];
    const float* Wv   = (const float*)d_in[5];
    const float* bv   = (const float*)d_in[6];
    const float* Wo   = (const float*)d_in[7];
    const float* bo   = (const float*)d_in[8];
    const float* proj = (const float*)d_in[9];
    float* out = (float*)d_out;

    cudaFuncSetAttribute(chunk_sums, cudaFuncAttributeMaxDynamicSharedMemorySize,
                         (CHK*MP + CHK*DH)*4);
    cudaFuncSetAttribute(out_chunk, cudaFuncAttributeMaxDynamicSharedMemorySize,
                         (128*129 + 128*64)*4);

    float *lin,*q,*k,*v,*qp,*kp,*attn,*projn;
    cudaGetSymbolAddress((void**)&lin,   g_lin);
    cudaGetSymbolAddress((void**)&q,     g_q);
    cudaGetSymbolAddress((void**)&k,     g_k);
    cudaGetSymbolAddress((void**)&v,     g_v);
    cudaGetSymbolAddress((void**)&qp,    g_qp);
    cudaGetSymbolAddress((void**)&kp,    g_kp);
    cudaGetSymbolAddress((void**)&attn,  g_attn);
    cudaGetSymbolAddress((void**)&projn, g_projn);

    prep_kernel<<<(MP*DH+255)/256, 256>>>(proj);

    dim3 gqkv(DM/128, ROWS/128);   // (8, 64)
    sgemm_tf32<<<gqkv,256>>>(ROWS, DM, DM, x, Wq, lin, DM, nullptr);
    split_heads<<<ROWS*DM/256,256>>>(lin, bq, q);
    sgemm_tf32<<<gqkv,256>>>(ROWS, DM, DM, x, Wk, lin, DM, nullptr);
    split_heads<<<ROWS*DM/256,256>>>(lin, bk, k);
    sgemm_tf32<<<gqkv,256>>>(ROWS, DM, DM, x, Wv, lin, DM, nullptr);
    split_heads<<<ROWS*DM/256,256>>>(lin, bv, v);

    dim3 gdd((MP+127)/128, TOK/128);  // (3, 1024)
    sgemm_tf32<<<gdd,256>>>(TOK, MP, DH, q, projn, qp, MP, nullptr);
    sgemm_tf32<<<gdd,256>>>(TOK, MP, DH, k, projn, kp, MP, nullptr);

    feat_apply<<<TOK/8,256>>>(q, qp, 1);
    kmax_kernel<<<TOK/8,256>>>(kp);
    feat_apply<<<TOK/8,256>>>(k, kp, 0);

    chunk_sums<<<BH*NC,256,(CHK*MP + CHK*DH)*4>>>();
    scan_chunks<<<BH,256>>>();
    out_chunk<<<BH*NC,256,(128*129 + 128*64)*4>>>();

    sgemm_tf32<<<gqkv,256>>>(ROWS, DM, DM, attn, Wo, out, DM, bo);
}

// round 4
// speedup vs baseline: 2.2893x; 1.3808x over previous
#include <cuda_runtime.h>
#include <math.h>

#define BSZ 2
#define HEADS 16
#define SEQ 4096
#define DH 64
#define DM 1024
#define MF 266
#define MP 272
#define CHK 128
#define NC 32
#define BH 32
#define TOK (BH*SEQ)
#define ROWS (BSZ*SEQ)

#define NORMALIZER 0.35355339059327373f
#define DIAG_COEF 0.0625f
#define RATIO 0.061313933948496584f
#define KEPS 1e-4f
#define CEPS 1e-6f

// ---------------- static scratch ----------------
__device__ float g_lin[(size_t)ROWS*DM];
__device__ float g_q[(size_t)TOK*DH];
__device__ float g_k[(size_t)TOK*DH];
__device__ float g_v[(size_t)TOK*DH];
__device__ float g_qp[(size_t)TOK*MP];
__device__ float g_kp[(size_t)TOK*MP];
__device__ float g_csum[(size_t)BH*NC*MP*DH];
__device__ float g_zsum[(size_t)BH*NC*MP];
__device__ float g_attn[(size_t)ROWS*DM];
__device__ float g_projn[384*DH];          // padded to 384 rows (zeros)
__device__ float g_xr[(size_t)ROWS*DM];    // tf32-rounded x
__device__ float g_wr[(size_t)DM*DM];      // tf32-rounded weight scratch
__device__ unsigned int g_kmax_bits;

__device__ __forceinline__ unsigned int enc_f(float f){
    unsigned int u = __float_as_uint(f);
    return (u & 0x80000000u) ? ~u : (u | 0x80000000u);
}
__device__ __forceinline__ float dec_f(unsigned int u){
    return (u & 0x80000000u) ? __uint_as_float(u & 0x7fffffffu)
                             : __uint_as_float(~u);
}
__device__ __forceinline__ float tf32f(float f){
    unsigned r; asm("cvt.rna.tf32.f32 %0, %1;" : "=r"(r) : "f"(f));
    return __uint_as_float(r);
}
__device__ __forceinline__ unsigned sptr(const void* p){
    return (unsigned)__cvta_generic_to_shared(p);
}
#define CP16(dst,src) asm volatile("cp.async.cg.shared.global [%0], [%1], 16;"::"r"(dst),"l"(src))
#define CPCOMMIT() asm volatile("cp.async.commit_group;")
#define CPWAIT1() asm volatile("cp.async.wait_group 1;")
#define CPWAIT0() asm volatile("cp.async.wait_group 0;")
#define LDM4(r0,r1,r2,r3,addr) \
    asm volatile("ldmatrix.sync.aligned.m8n8.x4.shared.b16 {%0,%1,%2,%3}, [%4];" \
        :"=r"(r0),"=r"(r1),"=r"(r2),"=r"(r3):"r"(addr))
#define MMA(acc,a0,a1,a2,a3,b0,b1) \
    asm volatile("mma.sync.aligned.m16n8k8.row.col.f32.tf32.tf32.f32 " \
        "{%0,%1,%2,%3},{%4,%5,%6,%7},{%8,%9},{%0,%1,%2,%3};" \
        :"+f"(acc[0]),"+f"(acc[1]),"+f"(acc[2]),"+f"(acc[3]) \
        :"r"(a0),"r"(a1),"r"(a2),"r"(a3),"r"(b0),"r"(b1))

// ---------------- prep ----------------
__global__ void prep_kernel(const float* __restrict__ proj){
    int idx = blockIdx.x*256 + threadIdx.x;
    if (idx == 0) g_kmax_bits = 0u;
    if (idx < 384*DH){
        int m = idx / DH, d = idx % DH;
        g_projn[idx] = (m < MF) ? tf32f(proj[m*DH + d] * NORMALIZER) : 0.f;
    }
}

__global__ void round_copy(const float* __restrict__ s, float* __restrict__ d, int n4){
    int i = blockIdx.x*256 + threadIdx.x;
    if (i < n4){
        float4 v = ((const float4*)s)[i];
        v.x=tf32f(v.x); v.y=tf32f(v.y); v.z=tf32f(v.z); v.w=tf32f(v.w);
        ((float4*)d)[i] = v;
    }
}

// ---------------- tf32 GEMM v3: cp.async + ldmatrix -------------------------
// C[M,N] = A[M,K]*B[N,K]^T (+bias). Inputs pre-rounded to tf32.
// Tiles: CTA 128x128, k-step 16, 3-stage cp.async, 8 warps of 64x32.
__global__ __launch_bounds__(256,2)
void sgemm_tc(int M, int N, int K, const float* __restrict__ A,
              const float* __restrict__ B, float* __restrict__ C,
              int ldc, const float* __restrict__ bias)
{
    __shared__ float sm[3*4096];
    const int kt = K >> 4;
    const int tid=threadIdx.x, lane=tid&31, wid=tid>>5;
    const int m0=blockIdx.y*128, n0=blockIdx.x*128;
    const int wm=(wid&1)*64, wn=(wid>>1)*32;
    const int qr=lane>>2, qc=lane&3;
    const int lrow=(lane&7)+(lane&8);
    const int lco=lane>>4;

    float acc[4][4][4];
    #pragma unroll
    for(int i=0;i<4;i++)
        #pragma unroll
        for(int j=0;j<4;j++){acc[i][j][0]=0;acc[i][j][1]=0;acc[i][j][2]=0;acc[i][j][3]=0;}

#define G_ISSUE(t) { int s_=(t)%3; float* As_=sm+s_*4096; float* Bs_=As_+2048; \
    const float* Ag_=A+(size_t)m0*K+(size_t)(t)*16; \
    const float* Bg_=B+(size_t)n0*K+(size_t)(t)*16; \
    _Pragma("unroll") for(int h=0;h<2;h++){ \
      int id=tid+h*256; int m=id>>2, cc=id&3, cs=cc^((m>>1)&3); \
      CP16(sptr(As_+m*16+cs*4), Ag_+(size_t)m*K+cc*4); \
      CP16(sptr(Bs_+m*16+cs*4), Bg_+(size_t)m*K+cc*4); } \
    CPCOMMIT(); }

    G_ISSUE(0);
    if (kt>1) G_ISSUE(1);

    for (int t=0;t<kt;t++){
        if (t+1<kt) CPWAIT1(); else CPWAIT0();
        __syncthreads();
        float* As = sm + (t%3)*4096;
        float* Bs = As + 2048;
        #pragma unroll
        for (int k8=0;k8<2;k8++){
            unsigned a[4][4];
            #pragma unroll
            for (int mf=0;mf<4;mf++){
                int row = wm + mf*16 + lrow;
                int c = 2*k8 + lco;
                unsigned ad = sptr(As + row*16 + (c ^ ((row>>1)&3))*4);
                LDM4(a[mf][0],a[mf][1],a[mf][2],a[mf][3],ad);
            }
            unsigned b[4][2];
            #pragma unroll
            for (int p=0;p<2;p++){
                int row = wn + p*16 + lrow;
                int c = 2*k8 + lco;
                unsigned ad = sptr(Bs + row*16 + (c ^ ((row>>1)&3))*4);
                unsigned r0,r1,r2,r3; LDM4(r0,r1,r2,r3,ad);
                b[2*p][0]=r0; b[2*p+1][0]=r1; b[2*p][1]=r2; b[2*p+1][1]=r3;
            }
            #pragma unroll
            for (int mf=0;mf<4;mf++)
                #pragma unroll
                for (int nf=0;nf<4;nf++)
                    MMA(acc[mf][nf],a[mf][0],a[mf][1],a[mf][2],a[mf][3],
                        b[nf][0],b[nf][1]);
        }
        __syncthreads();
        if (t+2<kt) G_ISSUE(t+2);
    }

    #pragma unroll
    for (int mf=0;mf<4;mf++){
        #pragma unroll
        for (int nf=0;nf<4;nf++){
            int row = m0 + wm + mf*16 + qr;
            int col = n0 + wn + nf*8 + qc*2;
            if (col < N){
                float b0 = bias ? bias[col]   : 0.f;
                float b1 = bias ? bias[col+1] : 0.f;
                float2 v0; v0.x=acc[mf][nf][0]+b0; v0.y=acc[mf][nf][1]+b1;
                float2 v1; v1.x=acc[mf][nf][2]+b0; v1.y=acc[mf][nf][3]+b1;
                *(float2*)(C + (size_t)row*ldc + col)     = v0;
                *(float2*)(C + (size_t)(row+8)*ldc + col) = v1;
            }
        }
    }
#undef G_ISSUE
}

// ---------------- split heads (tf32-rounded output) --------------------------
__global__ void split_heads(const float* __restrict__ lin,
                            const float* __restrict__ bias,
                            float* __restrict__ dst)
{
    int idx = blockIdx.x*256 + threadIdx.x;
    int r = idx >> 10, c = idx & 1023;
    int b = r >> 12, n = r & 4095;
    int h = c >> 6,  d = c & 63;
    dst[(((size_t)(b*HEADS + h))*SEQ + n)*DH + d] = tf32f(lin[idx] + bias[c]);
}

// ---------------- global max over k's data_dash ------------------------------
__global__ void kmax_kernel(const float* __restrict__ kp_)
{
    __shared__ float smx[8];
    int warp = threadIdx.x >> 5, lane = threadIdx.x & 31;
    size_t row = (size_t)blockIdx.x*8 + warp;
    const float* dd = kp_ + row*MP;
    float mx = -3.4e38f;
    #pragma unroll
    for (int i=0;i<9;i++){
        int m = i*32 + lane;
        if (m < MF) mx = fmaxf(mx, dd[m]);
    }
    #pragma unroll
    for (int o=16;o;o>>=1) mx = fmaxf(mx, __shfl_xor_sync(0xffffffffu, mx, o));
    if (lane==0) smx[warp]=mx;
    __syncthreads();
    if (threadIdx.x==0){
        float m = smx[0];
        #pragma unroll
        for (int w=1;w<8;w++) m = fmaxf(m, smx[w]);
        atomicMax(&g_kmax_bits, enc_f(m));
    }
}

// ---------------- exp feature map in-place (tf32-rounded output) -------------
__global__ void feat_apply(const float* __restrict__ data,
                           float* __restrict__ ddb, int is_query)
{
    int warp = threadIdx.x >> 5, lane = threadIdx.x & 31;
    size_t row = (size_t)blockIdx.x*8 + warp;
    float2 qq = ((const float2*)(data + row*DH))[lane];
    float s = qq.x*qq.x + qq.y*qq.y;
    #pragma unroll
    for (int o=16;o;o>>=1) s += __shfl_xor_sync(0xffffffffu, s, o);
    float diag = DIAG_COEF * s;

    float* dd = ddb + row*MP;
    float vals[9];
    float mx;
    if (is_query){
        mx = -3.4e38f;
        #pragma unroll
        for (int i=0;i<9;i++){
            int m = i*32 + lane;
            float v = (m < MP) ? dd[m] : 0.f;
            vals[i] = v;
            if (m < MF) mx = fmaxf(mx, v);
        }
        #pragma unroll
        for (int o=16;o;o>>=1) mx = fmaxf(mx, __shfl_xor_sync(0xffffffffu, mx, o));
    } else {
        #pragma unroll
        for (int i=0;i<9;i++){
            int m = i*32 + lane;
            vals[i] = (m < MP) ? dd[m] : 0.f;
        }
        mx = dec_f(g_kmax_bits);
    }
    #pragma unroll
    for (int i=0;i<9;i++){
        int m = i*32 + lane;
        if (m < MP)
            dd[m] = (m < MF) ? tf32f(RATIO*(expf(vals[i]-diag-mx)+KEPS)) : 0.f;
    }
}

// ---------------- per-chunk Csum = K'^T V, zsum = colsum(K') -----------------
extern __shared__ float s_dyn[];
__global__ __launch_bounds__(256)
void chunk_sums()
{
    float* Ks = s_dyn;
    float* Vs = s_dyn + CHK*MP;
    int blk = blockIdx.x;
    size_t tok0 = (size_t)blk * CHK;
    int tid = threadIdx.x;

    const float4* ksrc = (const float4*)(g_kp + tok0*MP);
    float4* kdst = (float4*)Ks;
    #pragma unroll
    for (int j=0;j<34;j++) kdst[j*256 + tid] = ksrc[j*256 + tid];
    const float4* vsrc = (const float4*)(g_v + tok0*DH);
    float4* vdst = (float4*)Vs;
    #pragma unroll
    for (int j=0;j<8;j++) vdst[j*256 + tid] = vsrc[j*256 + tid];
    __syncthreads();

    int d2 = tid & 31;
    int mg = tid >> 5;
    float2 acc[34];
    #pragma unroll
    for (int i=0;i<34;i++){ acc[i].x=0.f; acc[i].y=0.f; }
    const float2* V2 = (const float2*)Vs;
    for (int t=0;t<CHK;t++){
        float2 v = V2[t*32 + d2];
        const float* kr = Ks + t*MP + mg*34;
        #pragma unroll
        for (int mi=0;mi<34;mi++){
            float kk = kr[mi];
            acc[mi].x = fmaf(kk, v.x, acc[mi].x);
            acc[mi].y = fmaf(kk, v.y, acc[mi].y);
        }
    }
    float* cdst = g_csum + (size_t)blk*MP*DH;
    #pragma unroll
    for (int mi=0;mi<34;mi++){
        int m = mg*34 + mi;
        float2 o; o.x=acc[mi].x; o.y=acc[mi].y;
        ((float2*)(cdst + (size_t)m*DH))[d2] = o;
    }
    for (int m = tid; m < MP; m += 256){
        float sm = 0.f;
        for (int t=0;t<CHK;t++) sm += Ks[t*MP + m];
        g_zsum[(size_t)blk*MP + m] = sm;
    }
}

// ---------------- exclusive scan over chunks (tf32-rounded stores) ----------
__global__ __launch_bounds__(256)
void scan_chunks()
{
    int bh = blockIdx.x, tid = threadIdx.x;
    float2 st[34];
    #pragma unroll
    for (int i=0;i<34;i++){ st[i].x=0.f; st[i].y=0.f; }
    float2 zst; zst.x=0.f; zst.y=0.f;
    bool zact = tid < 136;
    for (int c=0;c<NC;c++){
        float2* p = (float2*)(g_csum + ((size_t)bh*NC + c)*MP*DH);
        #pragma unroll
        for (int i=0;i<34;i++){
            int j = i*256 + tid;
            float2 t = p[j];
            float2 o; o.x=tf32f(st[i].x); o.y=tf32f(st[i].y);
            p[j] = o;
            st[i].x += t.x; st[i].y += t.y;
        }
        if (zact){
            float2* zp = (float2*)(g_zsum + ((size_t)bh*NC + c)*MP);
            float2 t = zp[tid];
            float2 o; o.x=tf32f(zst.x); o.y=tf32f(zst.y);
            zp[tid] = o;
            zst.x += t.x; zst.y += t.y;
        }
    }
}

// ---------------- out_chunk via tensor cores ---------------------------------
// acc_O cols 0..63 = output, col64+col65 = denominator (z/rowsum + eps*sum(q)).
#define OC_SMEM ((128*132 + 128*72)*4)
__global__ __launch_bounds__(256)
void out_chunk_mma()
{
    float* Am = s_dyn;                 // [128][132]  (phase2; phase1 tiles live inside)
    float* Vt = s_dyn + 128*132;       // [128][72]
    const int tid=threadIdx.x, lane=tid&31, wid=tid>>5;
    const int blk=blockIdx.x, bh=blk>>5, c=blk&31;
    const size_t tok0=(size_t)blk*CHK;
    const float* Sg = g_csum + (size_t)blk*MP*DH;
    const float* zg = g_zsum + (size_t)blk*MP;
    const int qr=lane>>2, qc=lane&3;
    const int lrow=(lane&7)+(lane&8);
    const int lco=lane>>4;

    // Vt: cols 0-63 = v, col 64 = 1, 65-71 = 0
    for (int i=tid;i<128*18;i+=256){
        int r=i/18, cc=i%18;
        float4 v;
        if (cc<16) v = *(const float4*)(g_v + (tok0+r)*DH + cc*4);
        else if (cc==16) v = make_float4(1.f,0.f,0.f,0.f);
        else v = make_float4(0.f,0.f,0.f,0.f);
        *(float4*)(Vt + r*72 + cc*4) = v;
    }

    float accA[16][4];
    float accO[9][4];
    #pragma unroll
    for(int i=0;i<16;i++){accA[i][0]=0;accA[i][1]=0;accA[i][2]=0;accA[i][3]=0;}
    #pragma unroll
    for(int i=0;i<9;i++){accO[i][0]=0;accO[i][1]=0;accO[i][2]=0;accO[i][3]=0;}

    const float cepsT = tf32f(CEPS);

#define OC_ISSUE(t) { int s_=(t)&1; \
    float* Qt_=s_dyn+s_*4096; float* Kt_=Qt_+2048; float* St_=s_dyn+8192+s_*1152; \
    const float* Qg_=g_qp+tok0*MP+(t)*16; const float* Kg_=g_kp+tok0*MP+(t)*16; \
    _Pragma("unroll") for(int h=0;h<2;h++){ \
      int id=tid+h*256; int m=id>>2, cc_=id&3, cs=cc_^((m>>1)&3); \
      CP16(sptr(Qt_+m*16+cs*4), Qg_+(size_t)m*MP+cc_*4); \
      CP16(sptr(Kt_+m*16+cs*4), Kg_+(size_t)m*MP+cc_*4); } \
    { int k_=tid>>4, cc_=tid&15; \
      CP16(sptr(St_+k_*72+cc_*4), Sg+(size_t)((t)*16+k_)*DH+cc_*4); } \
    if (tid<16){ St_[tid*72+64]=zg[(t)*16+tid]; St_[tid*72+65]=cepsT; \
      _Pragma("unroll") for(int j=66;j<72;j++) St_[tid*72+j]=0.f; } \
    CPCOMMIT(); }

    OC_ISSUE(0);
    for (int t=0;t<17;t++){
        if (t+1<17) OC_ISSUE(t+1);
        if (t<16) CPWAIT1(); else CPWAIT0();
        __syncthreads();
        float* Qt = s_dyn + (t&1)*4096;
        float* Kt = Qt + 2048;
        float* St = s_dyn + 8192 + (t&1)*1152;
        #pragma unroll
        for (int k8=0;k8<2;k8++){
            unsigned a[4];
            {
                int row = wid*16 + lrow;
                int cc_ = 2*k8 + lco;
                unsigned ad = sptr(Qt + row*16 + (cc_ ^ ((row>>1)&3))*4);
                LDM4(a[0],a[1],a[2],a[3],ad);
            }
            #pragma unroll
            for (int p=0;p<8;p++){
                int row = p*16 + lrow;
                int cc_ = 2*k8 + lco;
                unsigned ad = sptr(Kt + row*16 + (cc_ ^ ((row>>1)&3))*4);
                unsigned r0,r1,r2,r3; LDM4(r0,r1,r2,r3,ad);
                MMA(accA[2*p],  a[0],a[1],a[2],a[3], r0, r2);
                MMA(accA[2*p+1],a[0],a[1],a[2],a[3], r1, r3);
            }
            #pragma unroll
            for (int nf=0;nf<9;nf++){
                unsigned b0 = __float_as_uint(St[(k8*8+qc)*72   + nf*8+qr]);
                unsigned b1 = __float_as_uint(St[(k8*8+qc+4)*72 + nf*8+qr]);
                MMA(accO[nf], a[0],a[1],a[2],a[3], b0, b1);
            }
        }
        __syncthreads();
    }

    // write masked tf32 A to shared
    #pragma unroll
    for (int nf=0;nf<16;nf++){
        int col = nf*8 + qc*2;
        int r0 = wid*16 + qr, r1 = r0 + 8;
        Am[r0*132+col]   = (col   <= r0) ? tf32f(accA[nf][0]) : 0.f;
        Am[r0*132+col+1] = (col+1 <= r0) ? tf32f(accA[nf][1]) : 0.f;
        Am[r1*132+col]   = (col   <= r1) ? tf32f(accA[nf][2]) : 0.f;
        Am[r1*132+col+1] = (col+1 <= r1) ? tf32f(accA[nf][3]) : 0.f;
    }
    __syncthreads();

    // phase 2: accO += maskedA @ Vt
    for (int kt=0;kt<16;kt++){
        unsigned a[4];
        {
            int row = wid*16 + lrow;
            unsigned ad = sptr(Am + row*132 + (2*kt + lco)*4);
            LDM4(a[0],a[1],a[2],a[3],ad);
        }
        #pragma unroll
        for (int nf=0;nf<9;nf++){
            unsigned b0 = __float_as_uint(Vt[(kt*8+qc)*72   + nf*8+qr]);
            unsigned b1 = __float_as_uint(Vt[(kt*8+qc+4)*72 + nf*8+qr]);
            MMA(accO[nf], a[0],a[1],a[2],a[3], b0, b1);
        }
    }

    // denominators: col64+col65 (held by qc==0 lanes in frag 8)
    float d0 = accO[8][0] + accO[8][1];
    float d1 = accO[8][2] + accO[8][3];
    d0 = __shfl_sync(0xffffffffu, d0, lane & ~3);
    d1 = __shfl_sync(0xffffffffu, d1, lane & ~3);
    float inv0 = 1.f/d0, inv1 = 1.f/d1;

    int b = bh >> 4, h = bh & 15;
    int n0 = c*CHK + wid*16;
    #pragma unroll
    for (int nf=0;nf<8;nf++){
        int col = h*64 + nf*8 + qc*2;
        float* o0 = g_attn + ((size_t)(b*SEQ + n0 + qr))*DM + col;
        float* o1 = g_attn + ((size_t)(b*SEQ + n0 + qr + 8))*DM + col;
        o0[0] = tf32f(accO[nf][0]*inv0); o0[1] = tf32f(accO[nf][1]*inv0);
        o1[0] = tf32f(accO[nf][2]*inv1); o1[1] = tf32f(accO[nf][3]*inv1);
    }
#undef OC_ISSUE
}

// ---------------- launch ------------------------------------------------------
extern "C" void kernel_launch(void* const* d_in, const int* in_sizes, int n_in,
                              void* d_out, int out_size)
{
    (void)in_sizes; (void)n_in; (void)out_size;
    const float* x    = (const float*)d_in[0];
    const float* Wq   = (const float*)d_in[1];
    const float* bq   = (const float*)d_in[2];
    const float* Wk   = (const float*)d_in[3];
    const float* bk   = (const float*)d_in[4];
    const float* Wv   = (const float*)d_in[5];
    const float* bv   = (const float*)d_in[6];
    const float* Wo   = (const float*)d_in[7];
    const float* bo   = (const float*)d_in[8];
    const float* proj = (const float*)d_in[9];
    float* out = (float*)d_out;

    cudaFuncSetAttribute(chunk_sums, cudaFuncAttributeMaxDynamicSharedMemorySize,
                         (CHK*MP + CHK*DH)*4);
    cudaFuncSetAttribute(out_chunk_mma, cudaFuncAttributeMaxDynamicSharedMemorySize,
                         OC_SMEM);

    float *lin,*q,*k,*v,*qp,*kp,*attn,*projn,*xr,*wr;
    cudaGetSymbolAddress((void**)&lin,   g_lin);
    cudaGetSymbolAddress((void**)&q,     g_q);
    cudaGetSymbolAddress((void**)&k,     g_k);
    cudaGetSymbolAddress((void**)&v,     g_v);
    cudaGetSymbolAddress((void**)&qp,    g_qp);
    cudaGetSymbolAddress((void**)&kp,    g_kp);
    cudaGetSymbolAddress((void**)&attn,  g_attn);
    cudaGetSymbolAddress((void**)&projn, g_projn);
    cudaGetSymbolAddress((void**)&xr,    g_xr);
    cudaGetSymbolAddress((void**)&wr,    g_wr);

    prep_kernel<<<(384*DH+255)/256, 256>>>(proj);
    round_copy<<<(ROWS*DM/4+255)/256, 256>>>(x, xr, ROWS*DM/4);

    dim3 gqkv(DM/128, ROWS/128);
    round_copy<<<(DM*DM/4+255)/256, 256>>>(Wq, wr, DM*DM/4);
    sgemm_tc<<<gqkv,256>>>(ROWS, DM, DM, xr, wr, lin, DM, nullptr);
    split_heads<<<ROWS*DM/256,256>>>(lin, bq, q);
    round_copy<<<(DM*DM/4+255)/256, 256>>>(Wk, wr, DM*DM/4);
    sgemm_tc<<<gqkv,256>>>(ROWS, DM, DM, xr, wr, lin, DM, nullptr);
    split_heads<<<ROWS*DM/256,256>>>(lin, bk, k);
    round_copy<<<(DM*DM/4+255)/256, 256>>>(Wv, wr, DM*DM/4);
    sgemm_tc<<<gqkv,256>>>(ROWS, DM, DM, xr, wr, lin, DM, nullptr);
    split_heads<<<ROWS*DM/256,256>>>(lin, bv, v);

    dim3 gdd(3, TOK/128);
    sgemm_tc<<<gdd,256>>>(TOK, MP, DH, q, projn, qp, MP, nullptr);
    sgemm_tc<<<gdd,256>>>(TOK, MP, DH, k, projn, kp, MP, nullptr);

    feat_apply<<<TOK/8,256>>>(q, qp, 1);
    kmax_kernel<<<TOK/8,256>>>(kp);
    feat_apply<<<TOK/8,256>>>(k, kp, 0);

    chunk_sums<<<BH*NC,256,(CHK*MP + CHK*DH)*4>>>();
    scan_chunks<<<BH,256>>>();
    out_chunk_mma<<<BH*NC,256,OC_SMEM>>>();

    round_copy<<<(DM*DM/4+255)/256, 256>>>(Wo, wr, DM*DM/4);
    sgemm_tc<<<gqkv,256>>>(ROWS, DM, DM, attn, wr, out, DM, bo);
}

// round 5
// speedup vs baseline: 3.3417x; 1.4597x over previous
#include <cuda_runtime.h>
#include <math.h>

#define BSZ 2
#define HEADS 16
#define SEQ 4096
#define DH 64
#define DM 1024
#define MF 266
#define MP 272
#define CHK 128
#define NC 32
#define BH 32
#define TOK (BH*SEQ)
#define ROWS (BSZ*SEQ)

#define NORMALIZER 0.35355339059327373f
#define DIAG_COEF 0.0625f
#define RATIO 0.061313933948496584f
#define KEPS 1e-4f
#define CEPS 1e-6f

// ---------------- static scratch ----------------
__device__ float g_q[(size_t)TOK*DH];
__device__ float g_k[(size_t)TOK*DH];
__device__ float g_v[(size_t)TOK*DH];
__device__ float g_qp[(size_t)TOK*MP];
__device__ float g_kp[(size_t)TOK*MP];
__device__ float g_csum[(size_t)BH*NC*MP*DH];
__device__ float g_zsum[(size_t)BH*NC*MP];
__device__ float g_attn[(size_t)ROWS*DM];
__device__ float g_projn[384*DH];
__device__ float g_xr[(size_t)ROWS*DM];
__device__ float g_wr3[(size_t)3*DM*DM];
__device__ unsigned int g_kmax_bits;

__device__ __forceinline__ unsigned int enc_f(float f){
    unsigned int u = __float_as_uint(f);
    return (u & 0x80000000u) ? ~u : (u | 0x80000000u);
}
__device__ __forceinline__ float dec_f(unsigned int u){
    return (u & 0x80000000u) ? __uint_as_float(u & 0x7fffffffu)
                             : __uint_as_float(~u);
}
__device__ __forceinline__ float tf32f(float f){
    unsigned r; asm("cvt.rna.tf32.f32 %0, %1;" : "=r"(r) : "f"(f));
    return __uint_as_float(r);
}
__device__ __forceinline__ unsigned sptr(const void* p){
    return (unsigned)__cvta_generic_to_shared(p);
}
#define CP16(dst,src) asm volatile("cp.async.cg.shared.global [%0], [%1], 16;"::"r"(dst),"l"(src))
#define CPCOMMIT() asm volatile("cp.async.commit_group;")
#define CPWAIT1() asm volatile("cp.async.wait_group 1;")
#define CPWAIT0() asm volatile("cp.async.wait_group 0;")
#define LDM4(r0,r1,r2,r3,addr) \
    asm volatile("ldmatrix.sync.aligned.m8n8.x4.shared.b16 {%0,%1,%2,%3}, [%4];" \
        :"=r"(r0),"=r"(r1),"=r"(r2),"=r"(r3):"r"(addr))
#define MMA(acc,a0,a1,a2,a3,b0,b1) \
    asm volatile("mma.sync.aligned.m16n8k8.row.col.f32.tf32.tf32.f32 " \
        "{%0,%1,%2,%3},{%4,%5,%6,%7},{%8,%9},{%0,%1,%2,%3};" \
        :"+f"(acc[0]),"+f"(acc[1]),"+f"(acc[2]),"+f"(acc[3]) \
        :"r"(a0),"r"(a1),"r"(a2),"r"(a3),"r"(b0),"r"(b1))

// shared GEMM-core macros (128x128 CTA tile, k-step 16, 3-stage cp.async)
#define G_ISSUE(t,Abase,Bbase,Ksz) { int s_=(t)%3; float* As_=sm+s_*4096; float* Bs_=As_+2048; \
    const float* Ag_=(Abase)+(size_t)(t)*16; \
    const float* Bg_=(Bbase)+(size_t)(t)*16; \
    _Pragma("unroll") for(int h=0;h<2;h++){ \
      int id=tid+h*256; int m=id>>2, cc=id&3, cs=cc^((m>>1)&3); \
      CP16(sptr(As_+m*16+cs*4), Ag_+(size_t)m*(Ksz)+cc*4); \
      CP16(sptr(Bs_+m*16+cs*4), Bg_+(size_t)m*(Ksz)+cc*4); } \
    CPCOMMIT(); }

#define GEMM_CORE(Abase,Bbase,Ksz,kt) \
    G_ISSUE(0,Abase,Bbase,Ksz); \
    if ((kt)>1) G_ISSUE(1,Abase,Bbase,Ksz); \
    for (int t=0;t<(kt);t++){ \
        if (t+1<(kt)) CPWAIT1(); else CPWAIT0(); \
        __syncthreads(); \
        float* As = sm + (t%3)*4096; \
        float* Bs = As + 2048; \
        _Pragma("unroll") \
        for (int k8=0;k8<2;k8++){ \
            unsigned a[4][4]; \
            _Pragma("unroll") \
            for (int mf=0;mf<4;mf++){ \
                int row = wm + mf*16 + lrow; \
                int c = 2*k8 + lco; \
                unsigned ad = sptr(As + row*16 + (c ^ ((row>>1)&3))*4); \
                LDM4(a[mf][0],a[mf][1],a[mf][2],a[mf][3],ad); \
            } \
            unsigned b[4][2]; \
            _Pragma("unroll") \
            for (int p=0;p<2;p++){ \
                int row = wn + p*16 + lrow; \
                int c = 2*k8 + lco; \
                unsigned ad = sptr(Bs + row*16 + (c ^ ((row>>1)&3))*4); \
                unsigned r0,r1,r2,r3; LDM4(r0,r1,r2,r3,ad); \
                b[2*p][0]=r0; b[2*p+1][0]=r1; b[2*p][1]=r2; b[2*p+1][1]=r3; \
            } \
            _Pragma("unroll") \
            for (int mf=0;mf<4;mf++) \
                _Pragma("unroll") \
                for (int nf=0;nf<4;nf++) \
                    MMA(acc[mf][nf],a[mf][0],a[mf][1],a[mf][2],a[mf][3], \
                        b[nf][0],b[nf][1]); \
        } \
        __syncthreads(); \
        if (t+2<(kt)) G_ISSUE(t+2,Abase,Bbase,Ksz); \
    }

#define GEMM_PREAMBLE() \
    const int tid=threadIdx.x, lane=tid&31, wid=tid>>5; \
    const int wm=(wid&1)*64, wn=(wid>>1)*32; \
    const int qr=lane>>2, qc=lane&3; \
    const int lrow=(lane&7)+(lane&8); \
    const int lco=lane>>4; \
    float acc[4][4][4]; \
    _Pragma("unroll") \
    for(int i=0;i<4;i++) \
        _Pragma("unroll") \
        for(int j=0;j<4;j++){acc[i][j][0]=0;acc[i][j][1]=0;acc[i][j][2]=0;acc[i][j][3]=0;}

// ---------------- prep ----------------
__global__ void prep_kernel(const float* __restrict__ proj){
    int idx = blockIdx.x*256 + threadIdx.x;
    if (idx == 0) g_kmax_bits = 0u;
    if (idx < 384*DH){
        int m = idx / DH, d = idx % DH;
        g_projn[idx] = (m < MF) ? tf32f(proj[m*DH + d] * NORMALIZER) : 0.f;
    }
}

__global__ void round_copy(const float* __restrict__ s, float* __restrict__ d, int n4){
    int i = blockIdx.x*256 + threadIdx.x;
    if (i < n4){
        float4 v = ((const float4*)s)[i];
        v.x=tf32f(v.x); v.y=tf32f(v.y); v.z=tf32f(v.z); v.w=tf32f(v.w);
        ((float4*)d)[i] = v;
    }
}

// ---------------- fused QKV GEMM: epilogue writes split-head q/k/v ----------
__global__ __launch_bounds__(256,2)
void gemm_qkv(const float* __restrict__ bq, const float* __restrict__ bk,
              const float* __restrict__ bv)
{
    __shared__ float sm[3*4096];
    const int m0=blockIdx.y*128, n0=blockIdx.x*128;
    GEMM_PREAMBLE();
    const float* Abase = g_xr + (size_t)m0*DM;
    const float* Bbase = g_wr3 + (size_t)n0*DM;
    GEMM_CORE(Abase, Bbase, DM, 64);

    #pragma unroll
    for (int mf=0;mf<4;mf++){
        int tr0 = m0 + wm + mf*16 + qr;       // token row
        int b0 = tr0 >> 12, n_ = tr0 & 4095;
        #pragma unroll
        for (int nf=0;nf<4;nf++){
            int col = n0 + wn + nf*8 + qc*2;  // [0,3072)
            int sel = col >> 10;
            int c1  = col & 1023;
            int h = c1 >> 6, d = c1 & 63;
            const float* bias = (sel==0) ? bq : (sel==1) ? bk : bv;
            float* dst = (sel==0) ? g_q : (sel==1) ? g_k : g_v;
            float bb0 = bias[c1], bb1 = bias[c1+1];
            size_t base0 = (((size_t)(b0*HEADS+h))*SEQ + n_)*DH + d;
            size_t base1 = (((size_t)(b0*HEADS+h))*SEQ + n_ + 8)*DH + d;
            float2 v0; v0.x = tf32f(acc[mf][nf][0]+bb0); v0.y = tf32f(acc[mf][nf][1]+bb1);
            float2 v1; v1.x = tf32f(acc[mf][nf][2]+bb0); v1.y = tf32f(acc[mf][nf][3]+bb1);
            *(float2*)(dst + base0) = v0;
            *(float2*)(dst + base1) = v1;
        }
    }
}

// ---------------- feature GEMM (z=0: q, z=1: k with fused global-max) -------
__global__ __launch_bounds__(256,2)
void sgemm_feat()
{
    __shared__ float sm[3*4096];
    const int z = blockIdx.z;
    const float* A = z ? g_k : g_q;
    float* C = z ? g_kp : g_qp;
    const int m0=blockIdx.y*128, n0=blockIdx.x*128;
    GEMM_PREAMBLE();
    const float* Abase = A + (size_t)m0*DH;
    const float* Bbase = g_projn + (size_t)n0*DH;
    GEMM_CORE(Abase, Bbase, DH, 4);

    float mx = -3.4e38f;
    #pragma unroll
    for (int mf=0;mf<4;mf++){
        int row = m0 + wm + mf*16 + qr;
        #pragma unroll
        for (int nf=0;nf<4;nf++){
            int col = n0 + wn + nf*8 + qc*2;
            if (col < MP){
                float2 v0; v0.x=acc[mf][nf][0]; v0.y=acc[mf][nf][1];
                float2 v1; v1.x=acc[mf][nf][2]; v1.y=acc[mf][nf][3];
                *(float2*)(C + (size_t)row*MP + col)     = v0;
                *(float2*)(C + (size_t)(row+8)*MP + col) = v1;
                if (z){
                    if (col   < MF){ mx = fmaxf(mx, v0.x); mx = fmaxf(mx, v1.x); }
                    if (col+1 < MF){ mx = fmaxf(mx, v0.y); mx = fmaxf(mx, v1.y); }
                }
            }
        }
    }
    if (z){
        #pragma unroll
        for (int o=16;o;o>>=1) mx = fmaxf(mx, __shfl_xor_sync(0xffffffffu, mx, o));
        __syncthreads();
        if (lane==0) sm[wid] = mx;
        __syncthreads();
        if (tid==0){
            float m = sm[0];
            #pragma unroll
            for (int w=1;w<8;w++) m = fmaxf(m, sm[w]);
            atomicMax(&g_kmax_bits, enc_f(m));
        }
    }
}

// ---------------- exp feature map in-place -----------------------------------
__global__ void feat_apply(const float* __restrict__ data,
                           float* __restrict__ ddb, int is_query)
{
    int warp = threadIdx.x >> 5, lane = threadIdx.x & 31;
    size_t row = (size_t)blockIdx.x*8 + warp;
    float2 qq = ((const float2*)(data + row*DH))[lane];
    float s = qq.x*qq.x + qq.y*qq.y;
    #pragma unroll
    for (int o=16;o;o>>=1) s += __shfl_xor_sync(0xffffffffu, s, o);
    float diag = DIAG_COEF * s;

    float* dd = ddb + row*MP;
    float vals[9];
    float mx;
    if (is_query){
        mx = -3.4e38f;
        #pragma unroll
        for (int i=0;i<9;i++){
            int m = i*32 + lane;
            float v = (m < MP) ? dd[m] : 0.f;
            vals[i] = v;
            if (m < MF) mx = fmaxf(mx, v);
        }
        #pragma unroll
        for (int o=16;o;o>>=1) mx = fmaxf(mx, __shfl_xor_sync(0xffffffffu, mx, o));
    } else {
        #pragma unroll
        for (int i=0;i<9;i++){
            int m = i*32 + lane;
            vals[i] = (m < MP) ? dd[m] : 0.f;
        }
        mx = dec_f(g_kmax_bits);
    }
    #pragma unroll
    for (int i=0;i<9;i++){
        int m = i*32 + lane;
        if (m < MP)
            dd[m] = (m < MF) ? tf32f(RATIO*(expf(vals[i]-diag-mx)+KEPS)) : 0.f;
    }
}

// ---------------- per-chunk Csum = K'^T V, zsum = colsum(K') -----------------
extern __shared__ float s_dyn[];
__global__ __launch_bounds__(256)
void chunk_sums()
{
    float* Ks = s_dyn;
    float* Vs = s_dyn + CHK*MP;
    int blk = blockIdx.x;
    size_t tok0 = (size_t)blk * CHK;
    int tid = threadIdx.x;

    const float4* ksrc = (const float4*)(g_kp + tok0*MP);
    float4* kdst = (float4*)Ks;
    #pragma unroll
    for (int j=0;j<34;j++) kdst[j*256 + tid] = ksrc[j*256 + tid];
    const float4* vsrc = (const float4*)(g_v + tok0*DH);
    float4* vdst = (float4*)Vs;
    #pragma unroll
    for (int j=0;j<8;j++) vdst[j*256 + tid] = vsrc[j*256 + tid];
    __syncthreads();

    int d2 = tid & 31;
    int mg = tid >> 5;
    float2 acc[34];
    #pragma unroll
    for (int i=0;i<34;i++){ acc[i].x=0.f; acc[i].y=0.f; }
    const float2* V2 = (const float2*)Vs;
    for (int t=0;t<CHK;t++){
        float2 v = V2[t*32 + d2];
        const float* kr = Ks + t*MP + mg*34;
        #pragma unroll
        for (int mi=0;mi<34;mi++){
            float kk = kr[mi];
            acc[mi].x = fmaf(kk, v.x, acc[mi].x);
            acc[mi].y = fmaf(kk, v.y, acc[mi].y);
        }
    }
    float* cdst = g_csum + (size_t)blk*MP*DH;
    #pragma unroll
    for (int mi=0;mi<34;mi++){
        int m = mg*34 + mi;
        ((float2*)(cdst + (size_t)m*DH))[d2] = acc[mi];
    }
    for (int m = tid; m < MP; m += 256){
        float sm = 0.f;
        for (int t=0;t<CHK;t++) sm += Ks[t*MP + m];
        g_zsum[(size_t)blk*MP + m] = sm;
    }
}

// ---------------- parallel exclusive scan over chunks ------------------------
__global__ __launch_bounds__(256)
void scan_par()
{
    int bh = blockIdx.y;
    if (blockIdx.x < 34){
        int l = blockIdx.x*256 + threadIdx.x;               // float2 lane in [0,8704)
        float2* base = (float2*)(g_csum + (size_t)bh*NC*MP*DH) + l;
        const int stride = MP*DH/2;                         // 8704
        float sx=0.f, sy=0.f;
        #pragma unroll
        for (int c=0;c<NC;c++){
            float2 t = base[(size_t)c*stride];
            float2 o; o.x = tf32f(sx); o.y = tf32f(sy);
            base[(size_t)c*stride] = o;
            sx += t.x; sy += t.y;
        }
    } else {
        if (threadIdx.x < 136){
            float2* base = (float2*)(g_zsum + (size_t)bh*NC*MP) + threadIdx.x;
            const int stride = MP/2;                        // 136
            float sx=0.f, sy=0.f;
            #pragma unroll
            for (int c=0;c<NC;c++){
                float2 t = base[(size_t)c*stride];
                float2 o; o.x = tf32f(sx); o.y = tf32f(sy);
                base[(size_t)c*stride] = o;
                sx += t.x; sy += t.y;
            }
        }
    }
}

// ---------------- out_chunk via tensor cores ---------------------------------
#define OC_SMEM ((128*132 + 128*72)*4)
__global__ __launch_bounds__(256)
void out_chunk_mma()
{
    float* Am = s_dyn;
    float* Vt = s_dyn + 128*132;
    const int tid=threadIdx.x, lane=tid&31, wid=tid>>5;
    const int blk=blockIdx.x, bh=blk>>5, c=blk&31;
    const size_t tok0=(size_t)blk*CHK;
    const float* Sg = g_csum + (size_t)blk*MP*DH;
    const float* zg = g_zsum + (size_t)blk*MP;
    const int qr=lane>>2, qc=lane&3;
    const int lrow=(lane&7)+(lane&8);
    const int lco=lane>>4;

    for (int i=tid;i<128*18;i+=256){
        int r=i/18, cc=i%18;
        float4 v;
        if (cc<16) v = *(const float4*)(g_v + (tok0+r)*DH + cc*4);
        else if (cc==16) v = make_float4(1.f,0.f,0.f,0.f);
        else v = make_float4(0.f,0.f,0.f,0.f);
        *(float4*)(Vt + r*72 + cc*4) = v;
    }

    float accA[16][4];
    float accO[9][4];
    #pragma unroll
    for(int i=0;i<16;i++){accA[i][0]=0;accA[i][1]=0;accA[i][2]=0;accA[i][3]=0;}
    #pragma unroll
    for(int i=0;i<9;i++){accO[i][0]=0;accO[i][1]=0;accO[i][2]=0;accO[i][3]=0;}

    const float cepsT = tf32f(CEPS);

#define OC_ISSUE(t) { int s_=(t)&1; \
    float* Qt_=s_dyn+s_*4096; float* Kt_=Qt_+2048; float* St_=s_dyn+8192+s_*1152; \
    const float* Qg_=g_qp+tok0*MP+(t)*16; const float* Kg_=g_kp+tok0*MP+(t)*16; \
    _Pragma("unroll") for(int h=0;h<2;h++){ \
      int id=tid+h*256; int m=id>>2, cc_=id&3, cs=cc_^((m>>1)&3); \
      CP16(sptr(Qt_+m*16+cs*4), Qg_+(size_t)m*MP+cc_*4); \
      CP16(sptr(Kt_+m*16+cs*4), Kg_+(size_t)m*MP+cc_*4); } \
    { int k_=tid>>4, cc_=tid&15; \
      CP16(sptr(St_+k_*72+cc_*4), Sg+(size_t)((t)*16+k_)*DH+cc_*4); } \
    if (tid<16){ St_[tid*72+64]=zg[(t)*16+tid]; St_[tid*72+65]=cepsT; \
      _Pragma("unroll") for(int j=66;j<72;j++) St_[tid*72+j]=0.f; } \
    CPCOMMIT(); }

    OC_ISSUE(0);
    for (int t=0;t<17;t++){
        if (t+1<17) OC_ISSUE(t+1);
        if (t<16) CPWAIT1(); else CPWAIT0();
        __syncthreads();
        float* Qt = s_dyn + (t&1)*4096;
        float* Kt = Qt + 2048;
        float* St = s_dyn + 8192 + (t&1)*1152;
        #pragma unroll
        for (int k8=0;k8<2;k8++){
            unsigned a[4];
            {
                int row = wid*16 + lrow;
                int cc_ = 2*k8 + lco;
                unsigned ad = sptr(Qt + row*16 + (cc_ ^ ((row>>1)&3))*4);
                LDM4(a[0],a[1],a[2],a[3],ad);
            }
            #pragma unroll
            for (int p=0;p<8;p++){
                int row = p*16 + lrow;
                int cc_ = 2*k8 + lco;
                unsigned ad = sptr(Kt + row*16 + (cc_ ^ ((row>>1)&3))*4);
                unsigned r0,r1,r2,r3; LDM4(r0,r1,r2,r3,ad);
                MMA(accA[2*p],  a[0],a[1],a[2],a[3], r0, r2);
                MMA(accA[2*p+1],a[0],a[1],a[2],a[3], r1, r3);
            }
            #pragma unroll
            for (int nf=0;nf<9;nf++){
                unsigned b0 = __float_as_uint(St[(k8*8+qc)*72   + nf*8+qr]);
                unsigned b1 = __float_as_uint(St[(k8*8+qc+4)*72 + nf*8+qr]);
                MMA(accO[nf], a[0],a[1],a[2],a[3], b0, b1);
            }
        }
        __syncthreads();
    }

    #pragma unroll
    for (int nf=0;nf<16;nf++){
        int col = nf*8 + qc*2;
        int r0 = wid*16 + qr, r1 = r0 + 8;
        Am[r0*132+col]   = (col   <= r0) ? tf32f(accA[nf][0]) : 0.f;
        Am[r0*132+col+1] = (col+1 <= r0) ? tf32f(accA[nf][1]) : 0.f;
        Am[r1*132+col]   = (col   <= r1) ? tf32f(accA[nf][2]) : 0.f;
        Am[r1*132+col+1] = (col+1 <= r1) ? tf32f(accA[nf][3]) : 0.f;
    }
    __syncthreads();

    for (int kt=0;kt<16;kt++){
        unsigned a[4];
        {
            int row = wid*16 + lrow;
            unsigned ad = sptr(Am + row*132 + (2*kt + lco)*4);
            LDM4(a[0],a[1],a[2],a[3],ad);
        }
        #pragma unroll
        for (int nf=0;nf<9;nf++){
            unsigned b0 = __float_as_uint(Vt[(kt*8+qc)*72   + nf*8+qr]);
            unsigned b1 = __float_as_uint(Vt[(kt*8+qc+4)*72 + nf*8+qr]);
            MMA(accO[nf], a[0],a[1],a[2],a[3], b0, b1);
        }
    }

    float d0 = accO[8][0] + accO[8][1];
    float d1 = accO[8][2] + accO[8][3];
    d0 = __shfl_sync(0xffffffffu, d0, lane & ~3);
    d1 = __shfl_sync(0xffffffffu, d1, lane & ~3);
    float inv0 = 1.f/d0, inv1 = 1.f/d1;

    int b = bh >> 4, h = bh & 15;
    int n0 = c*CHK + wid*16;
    #pragma unroll
    for (int nf=0;nf<8;nf++){
        int col = h*64 + nf*8 + qc*2;
        float* o0 = g_attn + ((size_t)(b*SEQ + n0 + qr))*DM + col;
        float* o1 = g_attn + ((size_t)(b*SEQ + n0 + qr + 8))*DM + col;
        o0[0] = tf32f(accO[nf][0]*inv0); o0[1] = tf32f(accO[nf][1]*inv0);
        o1[0] = tf32f(accO[nf][2]*inv1); o1[1] = tf32f(accO[nf][3]*inv1);
    }
#undef OC_ISSUE
}

// ---------------- output projection GEMM -------------------------------------
__global__ __launch_bounds__(256,2)
void gemm_out(float* __restrict__ C, const float* __restrict__ bias)
{
    __shared__ float sm[3*4096];
    const int m0=blockIdx.y*128, n0=blockIdx.x*128;
    GEMM_PREAMBLE();
    const float* Abase = g_attn + (size_t)m0*DM;
    const float* Bbase = g_wr3 + (size_t)n0*DM;
    GEMM_CORE(Abase, Bbase, DM, 64);

    #pragma unroll
    for (int mf=0;mf<4;mf++){
        #pragma unroll
        for (int nf=0;nf<4;nf++){
            int row = m0 + wm + mf*16 + qr;
            int col = n0 + wn + nf*8 + qc*2;
            float b0 = bias[col], b1 = bias[col+1];
            float2 v0; v0.x=acc[mf][nf][0]+b0; v0.y=acc[mf][nf][1]+b1;
            float2 v1; v1.x=acc[mf][nf][2]+b0; v1.y=acc[mf][nf][3]+b1;
            *(float2*)(C + (size_t)row*DM + col)     = v0;
            *(float2*)(C + (size_t)(row+8)*DM + col) = v1;
        }
    }
}

// ---------------- launch ------------------------------------------------------
extern "C" void kernel_launch(void* const* d_in, const int* in_sizes, int n_in,
                              void* d_out, int out_size)
{
    (void)in_sizes; (void)n_in; (void)out_size;
    const float* x    = (const float*)d_in[0];
    const float* Wq   = (const float*)d_in[1];
    const float* bq   = (const float*)d_in[2];
    const float* Wk   = (const float*)d_in[3];
    const float* bk   = (const float*)d_in[4];
    const float* Wv   = (const float*)d_in[5];
    const float* bv   = (const float*)d_in[6];
    const float* Wo   = (const float*)d_in[7];
    const float* bo   = (const float*)d_in[8];
    const float* proj = (const float*)d_in[9];
    float* out = (float*)d_out;

    cudaFuncSetAttribute(chunk_sums, cudaFuncAttributeMaxDynamicSharedMemorySize,
                         (CHK*MP + CHK*DH)*4);
    cudaFuncSetAttribute(out_chunk_mma, cudaFuncAttributeMaxDynamicSharedMemorySize,
                         OC_SMEM);

    float *xr,*wr3;
    cudaGetSymbolAddress((void**)&xr,  g_xr);
    cudaGetSymbolAddress((void**)&wr3, g_wr3);

    prep_kernel<<<(384*DH+255)/256, 256>>>(proj);
    round_copy<<<(ROWS*DM/4+255)/256, 256>>>(x, xr, ROWS*DM/4);
    round_copy<<<(DM*DM/4+255)/256, 256>>>(Wq, wr3,            DM*DM/4);
    round_copy<<<(DM*DM/4+255)/256, 256>>>(Wk, wr3 +   DM*DM,  DM*DM/4);
    round_copy<<<(DM*DM/4+255)/256, 256>>>(Wv, wr3 + 2*DM*DM,  DM*DM/4);

    dim3 gq(3*DM/128, ROWS/128);   // (24, 64)
    gemm_qkv<<<gq,256>>>(bq, bk, bv);

    dim3 gf(3, TOK/128, 2);
    sgemm_feat<<<gf,256>>>();

    float *q,*k,*qp,*kp;
    cudaGetSymbolAddress((void**)&q,  g_q);
    cudaGetSymbolAddress((void**)&k,  g_k);
    cudaGetSymbolAddress((void**)&qp, g_qp);
    cudaGetSymbolAddress((void**)&kp, g_kp);
    feat_apply<<<TOK/8,256>>>(q, qp, 1);
    feat_apply<<<TOK/8,256>>>(k, kp, 0);

    chunk_sums<<<BH*NC,256,(CHK*MP + CHK*DH)*4>>>();
    dim3 gsc(35, BH);
    scan_par<<<gsc,256>>>();
    out_chunk_mma<<<BH*NC,256,OC_SMEM>>>();

    round_copy<<<(DM*DM/4+255)/256, 256>>>(Wo, wr3, DM*DM/4);
    dim3 go(DM/128, ROWS/128);
    gemm_out<<<go,256>>>(out, bo);
}

// round 7
// speedup vs baseline: 4.1601x; 1.2449x over previous
#include <cuda_runtime.h>
#include <cuda_fp16.h>
#include <math.h>

#define BSZ 2
#define HEADS 16
#define SEQ 4096
#define DH 64
#define DM 1024
#define MF 266
#define MP 272
#define CHK 128
#define NC 32
#define BH 32
#define TOK (BH*SEQ)
#define ROWS (BSZ*SEQ)

#define NORMALIZER 0.35355339059327373f
#define DIAG_COEF 0.0625f
#define RATIO 0.061313933948496584f
#define KEPS 1e-4f
#define CEPS 1e-6f

// ---------------- static scratch ----------------
__device__ float g_q[(size_t)TOK*DH];
__device__ float g_k[(size_t)TOK*DH];
__device__ float g_v[(size_t)TOK*DH];
__device__ float g_qp[(size_t)TOK*MP];
__device__ float g_kp[(size_t)TOK*MP];
__device__ float g_csum[(size_t)BH*NC*MP*DH];
__device__ float g_zsum[(size_t)BH*NC*MP];
__device__ __half g_attn[(size_t)ROWS*DM];
__device__ float g_projn[384*DH];
__device__ __half g_xh[(size_t)ROWS*DM];
__device__ __half g_wh3[(size_t)3*DM*DM];
__device__ unsigned int g_kmax_bits;

__device__ __forceinline__ unsigned int enc_f(float f){
    unsigned int u = __float_as_uint(f);
    return (u & 0x80000000u) ? ~u : (u | 0x80000000u);
}
__device__ __forceinline__ float dec_f(unsigned int u){
    return (u & 0x80000000u) ? __uint_as_float(u & 0x7fffffffu)
                             : __uint_as_float(~u);
}
__device__ __forceinline__ float tf32f(float f){
    unsigned r; asm("cvt.rna.tf32.f32 %0, %1;" : "=r"(r) : "f"(f));
    return __uint_as_float(r);
}
__device__ __forceinline__ unsigned sptr(const void* p){
    return (unsigned)__cvta_generic_to_shared(p);
}
#define CP16(dst,src) asm volatile("cp.async.cg.shared.global [%0], [%1], 16;"::"r"(dst),"l"(src))
#define CPCOMMIT() asm volatile("cp.async.commit_group;")
#define CPWAIT1() asm volatile("cp.async.wait_group 1;")
#define CPWAIT0() asm volatile("cp.async.wait_group 0;")
#define LDM4(r0,r1,r2,r3,addr) \
    asm volatile("ldmatrix.sync.aligned.m8n8.x4.shared.b16 {%0,%1,%2,%3}, [%4];" \
        :"=r"(r0),"=r"(r1),"=r"(r2),"=r"(r3):"r"(addr))
#define MMA(acc,a0,a1,a2,a3,b0,b1) \
    asm volatile("mma.sync.aligned.m16n8k8.row.col.f32.tf32.tf32.f32 " \
        "{%0,%1,%2,%3},{%4,%5,%6,%7},{%8,%9},{%0,%1,%2,%3};" \
        :"+f"(acc[0]),"+f"(acc[1]),"+f"(acc[2]),"+f"(acc[3]) \
        :"r"(a0),"r"(a1),"r"(a2),"r"(a3),"r"(b0),"r"(b1))
#define MMA16(acc,a0,a1,a2,a3,b0,b1) \
    asm volatile("mma.sync.aligned.m16n8k16.row.col.f32.f16.f16.f32 " \
        "{%0,%1,%2,%3},{%4,%5,%6,%7},{%8,%9},{%0,%1,%2,%3};" \
        :"+f"(acc[0]),"+f"(acc[1]),"+f"(acc[2]),"+f"(acc[3]) \
        :"r"(a0),"r"(a1),"r"(a2),"r"(a3),"r"(b0),"r"(b1))

// ================= fp16 GEMM core: C[128,128] = A[128,K]h * B[128,K]h^T =====
// k-step 32, 3-stage cp.async, 8 warps of 64x32, m16n8k16.
#define H_ISSUE(t,Abase,Bbase,Ksz) { int s_=(t)%3; \
    __half* As_=smh+s_*8192; __half* Bs_=As_+4096; \
    const __half* Ag_=(Abase)+(size_t)(t)*32; \
    const __half* Bg_=(Bbase)+(size_t)(t)*32; \
    _Pragma("unroll") for(int h=0;h<2;h++){ \
      int id=tid+h*256; int row=id>>2, cc=id&3; \
      unsigned sw=(unsigned)((cc^((row>>1)&3))*16); \
      CP16(sptr((char*)As_+row*64+sw), Ag_+(size_t)row*(Ksz)+cc*8); \
      CP16(sptr((char*)Bs_+row*64+sw), Bg_+(size_t)row*(Ksz)+cc*8); } \
    CPCOMMIT(); }

#define HGEMM_CORE(Abase,Bbase,Ksz,kt) \
    H_ISSUE(0,Abase,Bbase,Ksz); \
    if ((kt)>1) H_ISSUE(1,Abase,Bbase,Ksz); \
    for (int t=0;t<(kt);t++){ \
        if (t+1<(kt)) CPWAIT1(); else CPWAIT0(); \
        __syncthreads(); \
        __half* As = smh + (t%3)*8192; \
        __half* Bs = As + 4096; \
        _Pragma("unroll") \
        for (int k16=0;k16<2;k16++){ \
            unsigned a[4][4]; \
            _Pragma("unroll") \
            for (int mf=0;mf<4;mf++){ \
                int row = wm + mf*16 + lrow; \
                int qd = 2*k16 + lco; \
                unsigned ad = sptr((char*)As + row*64 + ((qd^((row>>1)&3))*16)); \
                LDM4(a[mf][0],a[mf][1],a[mf][2],a[mf][3],ad); \
            } \
            unsigned b[4][2]; \
            _Pragma("unroll") \
            for (int p=0;p<2;p++){ \
                int row = wn + p*16 + lrow; \
                int qd = 2*k16 + lco; \
                unsigned ad = sptr((char*)Bs + row*64 + ((qd^((row>>1)&3))*16)); \
                unsigned r0,r1,r2,r3; LDM4(r0,r1,r2,r3,ad); \
                b[2*p][0]=r0; b[2*p+1][0]=r1; b[2*p][1]=r2; b[2*p+1][1]=r3; \
            } \
            _Pragma("unroll") \
            for (int mf=0;mf<4;mf++) \
                _Pragma("unroll") \
                for (int nf=0;nf<4;nf++) \
                    MMA16(acc[mf][nf],a[mf][0],a[mf][1],a[mf][2],a[mf][3], \
                          b[nf][0],b[nf][1]); \
        } \
        __syncthreads(); \
        if (t+2<(kt)) H_ISSUE(t+2,Abase,Bbase,Ksz); \
    }

#define GEMM_PREAMBLE() \
    const int tid=threadIdx.x, lane=tid&31, wid=tid>>5; \
    const int wm=(wid&1)*64, wn=(wid>>1)*32; \
    const int qr=lane>>2, qc=lane&3; \
    const int lrow=(lane&7)+(lane&8); \
    const int lco=lane>>4; \
    float acc[4][4][4]; \
    _Pragma("unroll") \
    for(int i=0;i<4;i++) \
        _Pragma("unroll") \
        for(int j=0;j<4;j++){acc[i][j][0]=0;acc[i][j][1]=0;acc[i][j][2]=0;acc[i][j][3]=0;}

// ---------------- fused QKV GEMM (fp16 in, fp32 out split-head) -------------
__global__ __launch_bounds__(256,2)
void hgemm_qkv(const float* __restrict__ bq, const float* __restrict__ bk,
               const float* __restrict__ bv)
{
    __shared__ __half smh[3*8192];
    const int m0=blockIdx.y*128, n0=blockIdx.x*128;
    GEMM_PREAMBLE();
    const __half* Abase = g_xh  + (size_t)m0*DM;
    const __half* Bbase = g_wh3 + (size_t)n0*DM;
    HGEMM_CORE(Abase, Bbase, DM, 32);

    #pragma unroll
    for (int mf=0;mf<4;mf++){
        int tr0 = m0 + wm + mf*16 + qr;
        int b0 = tr0 >> 12, n_ = tr0 & 4095;
        #pragma unroll
        for (int nf=0;nf<4;nf++){
            int col = n0 + wn + nf*8 + qc*2;
            int sel = col >> 10;
            int c1  = col & 1023;
            int h = c1 >> 6, d = c1 & 63;
            const float* bias = (sel==0) ? bq : (sel==1) ? bk : bv;
            float* dst = (sel==0) ? g_q : (sel==1) ? g_k : g_v;
            float bb0 = bias[c1], bb1 = bias[c1+1];
            size_t base0 = (((size_t)(b0*HEADS+h))*SEQ + n_)*DH + d;
            size_t base1 = (((size_t)(b0*HEADS+h))*SEQ + n_ + 8)*DH + d;
            float2 v0; v0.x = tf32f(acc[mf][nf][0]+bb0); v0.y = tf32f(acc[mf][nf][1]+bb1);
            float2 v1; v1.x = tf32f(acc[mf][nf][2]+bb0); v1.y = tf32f(acc[mf][nf][3]+bb1);
            *(float2*)(dst + base0) = v0;
            *(float2*)(dst + base1) = v1;
        }
    }
}

// ---------------- output projection GEMM (fp16 in) ---------------------------
__global__ __launch_bounds__(256,2)
void hgemm_out(float* __restrict__ C, const float* __restrict__ bias)
{
    __shared__ __half smh[3*8192];
    const int m0=blockIdx.y*128, n0=blockIdx.x*128;
    GEMM_PREAMBLE();
    const __half* Abase = g_attn + (size_t)m0*DM;
    const __half* Bbase = g_wh3  + (size_t)n0*DM;
    HGEMM_CORE(Abase, Bbase, DM, 32);

    #pragma unroll
    for (int mf=0;mf<4;mf++){
        #pragma unroll
        for (int nf=0;nf<4;nf++){
            int row = m0 + wm + mf*16 + qr;
            int col = n0 + wn + nf*8 + qc*2;
            float b0 = bias[col], b1 = bias[col+1];
            float2 v0; v0.x=acc[mf][nf][0]+b0; v0.y=acc[mf][nf][1]+b1;
            float2 v1; v1.x=acc[mf][nf][2]+b0; v1.y=acc[mf][nf][3]+b1;
            *(float2*)(C + (size_t)row*DM + col)     = v0;
            *(float2*)(C + (size_t)(row+8)*DM + col) = v1;
        }
    }
}

// ================= tf32 GEMM core (feature GEMM) =============================
#define G_ISSUE(t,Abase,Bbase,Ksz) { int s_=(t)%3; float* As_=sm+s_*4096; float* Bs_=As_+2048; \
    const float* Ag_=(Abase)+(size_t)(t)*16; \
    const float* Bg_=(Bbase)+(size_t)(t)*16; \
    _Pragma("unroll") for(int h=0;h<2;h++){ \
      int id=tid+h*256; int m=id>>2, cc=id&3, cs=cc^((m>>1)&3); \
      CP16(sptr(As_+m*16+cs*4), Ag_+(size_t)m*(Ksz)+cc*4); \
      CP16(sptr(Bs_+m*16+cs*4), Bg_+(size_t)m*(Ksz)+cc*4); } \
    CPCOMMIT(); }

#define GEMM_CORE(Abase,Bbase,Ksz,kt) \
    G_ISSUE(0,Abase,Bbase,Ksz); \
    if ((kt)>1) G_ISSUE(1,Abase,Bbase,Ksz); \
    for (int t=0;t<(kt);t++){ \
        if (t+1<(kt)) CPWAIT1(); else CPWAIT0(); \
        __syncthreads(); \
        float* As = sm + (t%3)*4096; \
        float* Bs = As + 2048; \
        _Pragma("unroll") \
        for (int k8=0;k8<2;k8++){ \
            unsigned a[4][4]; \
            _Pragma("unroll") \
            for (int mf=0;mf<4;mf++){ \
                int row = wm + mf*16 + lrow; \
                int c = 2*k8 + lco; \
                unsigned ad = sptr(As + row*16 + (c ^ ((row>>1)&3))*4); \
                LDM4(a[mf][0],a[mf][1],a[mf][2],a[mf][3],ad); \
            } \
            unsigned b[4][2]; \
            _Pragma("unroll") \
            for (int p=0;p<2;p++){ \
                int row = wn + p*16 + lrow; \
                int c = 2*k8 + lco; \
                unsigned ad = sptr(Bs + row*16 + (c ^ ((row>>1)&3))*4); \
                unsigned r0,r1,r2,r3; LDM4(r0,r1,r2,r3,ad); \
                b[2*p][0]=r0; b[2*p+1][0]=r1; b[2*p][1]=r2; b[2*p+1][1]=r3; \
            } \
            _Pragma("unroll") \
            for (int mf=0;mf<4;mf++) \
                _Pragma("unroll") \
                for (int nf=0;nf<4;nf++) \
                    MMA(acc[mf][nf],a[mf][0],a[mf][1],a[mf][2],a[mf][3], \
                        b[nf][0],b[nf][1]); \
        } \
        __syncthreads(); \
        if (t+2<(kt)) G_ISSUE(t+2,Abase,Bbase,Ksz); \
    }

// ---------------- prep ----------------
__global__ void prep_kernel(const float* __restrict__ proj){
    int idx = blockIdx.x*256 + threadIdx.x;
    if (idx == 0) g_kmax_bits = 0u;
    if (idx < 384*DH){
        int m = idx / DH, d = idx % DH;
        g_projn[idx] = (m < MF) ? tf32f(proj[m*DH + d] * NORMALIZER) : 0.f;
    }
}

__global__ void half_copy(const float* __restrict__ s, __half* __restrict__ d, int n4){
    int i = blockIdx.x*256 + threadIdx.x;
    if (i < n4){
        float4 v = ((const float4*)s)[i];
        __half2 h0 = __floats2half2_rn(v.x, v.y);
        __half2 h1 = __floats2half2_rn(v.z, v.w);
        ((__half2*)d)[i*2]   = h0;
        ((__half2*)d)[i*2+1] = h1;
    }
}

// ---------------- feature GEMM (z=0: q, z=1: k with fused global-max) -------
__global__ __launch_bounds__(256,2)
void sgemm_feat()
{
    __shared__ float sm[3*4096];
    const int z = blockIdx.z;
    const float* A = z ? g_k : g_q;
    float* C = z ? g_kp : g_qp;
    const int m0=blockIdx.y*128, n0=blockIdx.x*128;
    GEMM_PREAMBLE();
    const float* Abase = A + (size_t)m0*DH;
    const float* Bbase = g_projn + (size_t)n0*DH;
    GEMM_CORE(Abase, Bbase, DH, 4);

    float mx = -3.4e38f;
    #pragma unroll
    for (int mf=0;mf<4;mf++){
        int row = m0 + wm + mf*16 + qr;
        #pragma unroll
        for (int nf=0;nf<4;nf++){
            int col = n0 + wn + nf*8 + qc*2;
            if (col < MP){
                float2 v0; v0.x=acc[mf][nf][0]; v0.y=acc[mf][nf][1];
                float2 v1; v1.x=acc[mf][nf][2]; v1.y=acc[mf][nf][3];
                *(float2*)(C + (size_t)row*MP + col)     = v0;
                *(float2*)(C + (size_t)(row+8)*MP + col) = v1;
                if (z){
                    if (col   < MF){ mx = fmaxf(mx, v0.x); mx = fmaxf(mx, v1.x); }
                    if (col+1 < MF){ mx = fmaxf(mx, v0.y); mx = fmaxf(mx, v1.y); }
                }
            }
        }
    }
    if (z){
        #pragma unroll
        for (int o=16;o;o>>=1) mx = fmaxf(mx, __shfl_xor_sync(0xffffffffu, mx, o));
        __syncthreads();
        if (lane==0) sm[wid] = mx;
        __syncthreads();
        if (tid==0){
            float m = sm[0];
            #pragma unroll
            for (int w=1;w<8;w++) m = fmaxf(m, sm[w]);
            atomicMax(&g_kmax_bits, enc_f(m));
        }
    }
}

// ---------------- exp feature map in-place -----------------------------------
__global__ void feat_apply(const float* __restrict__ data,
                           float* __restrict__ ddb, int is_query)
{
    int warp = threadIdx.x >> 5, lane = threadIdx.x & 31;
    size_t row = (size_t)blockIdx.x*8 + warp;
    float2 qq = ((const float2*)(data + row*DH))[lane];
    float s = qq.x*qq.x + qq.y*qq.y;
    #pragma unroll
    for (int o=16;o;o>>=1) s += __shfl_xor_sync(0xffffffffu, s, o);
    float diag = DIAG_COEF * s;

    float* dd = ddb + row*MP;
    float vals[9];
    float mx;
    if (is_query){
        mx = -3.4e38f;
        #pragma unroll
        for (int i=0;i<9;i++){
            int m = i*32 + lane;
            float v = (m < MP) ? dd[m] : 0.f;
            vals[i] = v;
            if (m < MF) mx = fmaxf(mx, v);
        }
        #pragma unroll
        for (int o=16;o;o>>=1) mx = fmaxf(mx, __shfl_xor_sync(0xffffffffu, mx, o));
    } else {
        #pragma unroll
        for (int i=0;i<9;i++){
            int m = i*32 + lane;
            vals[i] = (m < MP) ? dd[m] : 0.f;
        }
        mx = dec_f(g_kmax_bits);
    }
    #pragma unroll
    for (int i=0;i<9;i++){
        int m = i*32 + lane;
        if (m < MP)
            dd[m] = (m < MF) ? tf32f(RATIO*(expf(vals[i]-diag-mx)+KEPS)) : 0.f;
    }
}

// ---------------- per-chunk Csum = K'^T V, zsum = colsum(K') -----------------
extern __shared__ float s_dyn[];
__global__ __launch_bounds__(256)
void chunk_sums()
{
    float* Ks = s_dyn;
    float* Vs = s_dyn + CHK*MP;
    int blk = blockIdx.x;
    size_t tok0 = (size_t)blk * CHK;
    int tid = threadIdx.x;

    const float4* ksrc = (const float4*)(g_kp + tok0*MP);
    float4* kdst = (float4*)Ks;
    #pragma unroll
    for (int j=0;j<34;j++) kdst[j*256 + tid] = ksrc[j*256 + tid];
    const float4* vsrc = (const float4*)(g_v + tok0*DH);
    float4* vdst = (float4*)Vs;
    #pragma unroll
    for (int j=0;j<8;j++) vdst[j*256 + tid] = vsrc[j*256 + tid];
    __syncthreads();

    int d2 = tid & 31;
    int mg = tid >> 5;
    float2 acc[34];
    #pragma unroll
    for (int i=0;i<34;i++){ acc[i].x=0.f; acc[i].y=0.f; }
    const float2* V2 = (const float2*)Vs;
    for (int t=0;t<CHK;t++){
        float2 v = V2[t*32 + d2];
        const float* kr = Ks + t*MP + mg*34;
        #pragma unroll
        for (int mi=0;mi<34;mi++){
            float kk = kr[mi];
            acc[mi].x = fmaf(kk, v.x, acc[mi].x);
            acc[mi].y = fmaf(kk, v.y, acc[mi].y);
        }
    }
    float* cdst = g_csum + (size_t)blk*MP*DH;
    #pragma unroll
    for (int mi=0;mi<34;mi++){
        int m = mg*34 + mi;
        ((float2*)(cdst + (size_t)m*DH))[d2] = acc[mi];
    }
    for (int m = tid; m < MP; m += 256){
        float sm = 0.f;
        for (int t=0;t<CHK;t++) sm += Ks[t*MP + m];
        g_zsum[(size_t)blk*MP + m] = sm;
    }
}

// ---------------- parallel exclusive scan over chunks ------------------------
__global__ __launch_bounds__(256)
void scan_par()
{
    int bh = blockIdx.y;
    if (blockIdx.x < 34){
        int l = blockIdx.x*256 + threadIdx.x;
        float2* base = (float2*)(g_csum + (size_t)bh*NC*MP*DH) + l;
        const int stride = MP*DH/2;
        float sx=0.f, sy=0.f;
        #pragma unroll
        for (int c=0;c<NC;c++){
            float2 t = base[(size_t)c*stride];
            float2 o; o.x = tf32f(sx); o.y = tf32f(sy);
            base[(size_t)c*stride] = o;
            sx += t.x; sy += t.y;
        }
    } else {
        if (threadIdx.x < 136){
            float2* base = (float2*)(g_zsum + (size_t)bh*NC*MP) + threadIdx.x;
            const int stride = MP/2;
            float sx=0.f, sy=0.f;
            #pragma unroll
            for (int c=0;c<NC;c++){
                float2 t = base[(size_t)c*stride];
                float2 o; o.x = tf32f(sx); o.y = tf32f(sy);
                base[(size_t)c*stride] = o;
                sx += t.x; sy += t.y;
            }
        }
    }
}

// ---------------- out_chunk via tensor cores (tf32) ---------------------------
#define OC_SMEM ((128*132 + 128*72)*4)
__global__ __launch_bounds__(256)
void out_chunk_mma()
{
    float* Am = s_dyn;
    float* Vt = s_dyn + 128*132;
    const int tid=threadIdx.x, lane=tid&31, wid=tid>>5;
    const int blk=blockIdx.x, bh=blk>>5, c=blk&31;
    const size_t tok0=(size_t)blk*CHK;
    const float* Sg = g_csum + (size_t)blk*MP*DH;
    const float* zg = g_zsum + (size_t)blk*MP;
    const int qr=lane>>2, qc=lane&3;
    const int lrow=(lane&7)+(lane&8);
    const int lco=lane>>4;

    for (int i=tid;i<128*18;i+=256){
        int r=i/18, cc=i%18;
        float4 v;
        if (cc<16) v = *(const float4*)(g_v + (tok0+r)*DH + cc*4);
        else if (cc==16) v = make_float4(1.f,0.f,0.f,0.f);
        else v = make_float4(0.f,0.f,0.f,0.f);
        *(float4*)(Vt + r*72 + cc*4) = v;
    }

    float accA[16][4];
    float accO[9][4];
    #pragma unroll
    for(int i=0;i<16;i++){accA[i][0]=0;accA[i][1]=0;accA[i][2]=0;accA[i][3]=0;}
    #pragma unroll
    for(int i=0;i<9;i++){accO[i][0]=0;accO[i][1]=0;accO[i][2]=0;accO[i][3]=0;}

    const float cepsT = tf32f(CEPS);

#define OC_ISSUE(t) { int s_=(t)&1; \
    float* Qt_=s_dyn+s_*4096; float* Kt_=Qt_+2048; float* St_=s_dyn+8192+s_*1152; \
    const float* Qg_=g_qp+tok0*MP+(t)*16; const float* Kg_=g_kp+tok0*MP+(t)*16; \
    _Pragma("unroll") for(int h=0;h<2;h++){ \
      int id=tid+h*256; int m=id>>2, cc_=id&3, cs=cc_^((m>>1)&3); \
      CP16(sptr(Qt_+m*16+cs*4), Qg_+(size_t)m*MP+cc_*4); \
      CP16(sptr(Kt_+m*16+cs*4), Kg_+(size_t)m*MP+cc_*4); } \
    { int k_=tid>>4, cc_=tid&15; \
      CP16(sptr(St_+k_*72+cc_*4), Sg+(size_t)((t)*16+k_)*DH+cc_*4); } \
    if (tid<16){ St_[tid*72+64]=zg[(t)*16+tid]; St_[tid*72+65]=cepsT; \
      _Pragma("unroll") for(int j=66;j<72;j++) St_[tid*72+j]=0.f; } \
    CPCOMMIT(); }

    OC_ISSUE(0);
    for (int t=0;t<17;t++){
        if (t+1<17) OC_ISSUE(t+1);
        if (t<16) CPWAIT1(); else CPWAIT0();
        __syncthreads();
        float* Qt = s_dyn + (t&1)*4096;
        float* Kt = Qt + 2048;
        float* St = s_dyn + 8192 + (t&1)*1152;
        #pragma unroll
        for (int k8=0;k8<2;k8++){
            unsigned a[4];
            {
                int row = wid*16 + lrow;
                int cc_ = 2*k8 + lco;
                unsigned ad = sptr(Qt + row*16 + (cc_ ^ ((row>>1)&3))*4);
                LDM4(a[0],a[1],a[2],a[3],ad);
            }
            #pragma unroll
            for (int p=0;p<8;p++){
                int row = p*16 + lrow;
                int cc_ = 2*k8 + lco;
                unsigned ad = sptr(Kt + row*16 + (cc_ ^ ((row>>1)&3))*4);
                unsigned r0,r1,r2,r3; LDM4(r0,r1,r2,r3,ad);
                MMA(accA[2*p],  a[0],a[1],a[2],a[3], r0, r2);
                MMA(accA[2*p+1],a[0],a[1],a[2],a[3], r1, r3);
            }
            #pragma unroll
            for (int nf=0;nf<9;nf++){
                unsigned b0 = __float_as_uint(St[(k8*8+qc)*72   + nf*8+qr]);
                unsigned b1 = __float_as_uint(St[(k8*8+qc+4)*72 + nf*8+qr]);
                MMA(accO[nf], a[0],a[1],a[2],a[3], b0, b1);
            }
        }
        __syncthreads();
    }

    #pragma unroll
    for (int nf=0;nf<16;nf++){
        int col = nf*8 + qc*2;
        int r0 = wid*16 + qr, r1 = r0 + 8;
        Am[r0*132+col]   = (col   <= r0) ? tf32f(accA[nf][0]) : 0.f;
        Am[r0*132+col+1] = (col+1 <= r0) ? tf32f(accA[nf][1]) : 0.f;
        Am[r1*132+col]   = (col   <= r1) ? tf32f(accA[nf][2]) : 0.f;
        Am[r1*132+col+1] = (col+1 <= r1) ? tf32f(accA[nf][3]) : 0.f;
    }
    __syncthreads();

    for (int kt=0;kt<16;kt++){
        unsigned a[4];
        {
            int row = wid*16 + lrow;
            unsigned ad = sptr(Am + row*132 + (2*kt + lco)*4);
            LDM4(a[0],a[1],a[2],a[3],ad);
        }
        #pragma unroll
        for (int nf=0;nf<9;nf++){
            unsigned b0 = __float_as_uint(Vt[(kt*8+qc)*72   + nf*8+qr]);
            unsigned b1 = __float_as_uint(Vt[(kt*8+qc+4)*72 + nf*8+qr]);
            MMA(accO[nf], a[0],a[1],a[2],a[3], b0, b1);
        }
    }

    float d0 = accO[8][0] + accO[8][1];
    float d1 = accO[8][2] + accO[8][3];
    d0 = __shfl_sync(0xffffffffu, d0, lane & ~3);
    d1 = __shfl_sync(0xffffffffu, d1, lane & ~3);
    float inv0 = 1.f/d0, inv1 = 1.f/d1;

    int b = bh >> 4, h = bh & 15;
    int n0 = c*CHK + wid*16;
    #pragma unroll
    for (int nf=0;nf<8;nf++){
        int col = h*64 + nf*8 + qc*2;
        __half2* o0 = (__half2*)(g_attn + ((size_t)(b*SEQ + n0 + qr))*DM + col);
        __half2* o1 = (__half2*)(g_attn + ((size_t)(b*SEQ + n0 + qr + 8))*DM + col);
        *o0 = __floats2half2_rn(accO[nf][0]*inv0, accO[nf][1]*inv0);
        *o1 = __floats2half2_rn(accO[nf][2]*inv1, accO[nf][3]*inv1);
    }
#undef OC_ISSUE
}

// ---------------- launch ------------------------------------------------------
extern "C" void kernel_launch(void* const* d_in, const int* in_sizes, int n_in,
                              void* d_out, int out_size)
{
    (void)in_sizes; (void)n_in; (void)out_size;
    const float* x    = (const float*)d_in[0];
    const float* Wq   = (const float*)d_in[1];
    const float* bq   = (const float*)d_in[2];
    const float* Wk   = (const float*)d_in[3];
    const float* bk   = (const float*)d_in[4];
    const float* Wv   = (const float*)d_in[5];
    const float* bv   = (const float*)d_in[6];
    const float* Wo   = (const float*)d_in[7];
    const float* bo   = (const float*)d_in[8];
    const float* proj = (const float*)d_in[9];
    float* out = (float*)d_out;

    cudaFuncSetAttribute(chunk_sums, cudaFuncAttributeMaxDynamicSharedMemorySize,
                         (CHK*MP + CHK*DH)*4);
    cudaFuncSetAttribute(out_chunk_mma, cudaFuncAttributeMaxDynamicSharedMemorySize,
                         OC_SMEM);

    __half *xh,*wh3;
    cudaGetSymbolAddress((void**)&xh,  g_xh);
    cudaGetSymbolAddress((void**)&wh3, g_wh3);

    prep_kernel<<<(384*DH+255)/256, 256>>>(proj);
    half_copy<<<(ROWS*DM/4+255)/256, 256>>>(x, xh, ROWS*DM/4);
    half_copy<<<(DM*DM/4+255)/256, 256>>>(Wq, wh3,           DM*DM/4);
    half_copy<<<(DM*DM/4+255)/256, 256>>>(Wk, wh3 +   DM*DM, DM*DM/4);
    half_copy<<<(DM*DM/4+255)/256, 256>>>(Wv, wh3 + 2*DM*DM, DM*DM/4);

    dim3 gq(3*DM/128, ROWS/128);   // (24, 64)
    hgemm_qkv<<<gq,256>>>(bq, bk, bv);

    dim3 gf(3, TOK/128, 2);
    sgemm_feat<<<gf,256>>>();

    float *q,*k,*qp,*kp;
    cudaGetSymbolAddress((void**)&q,  g_q);
    cudaGetSymbolAddress((void**)&k,  g_k);
    cudaGetSymbolAddress((void**)&qp, g_qp);
    cudaGetSymbolAddress((void**)&kp, g_kp);
    feat_apply<<<TOK/8,256>>>(q, qp, 1);
    feat_apply<<<TOK/8,256>>>(k, kp, 0);

    chunk_sums<<<BH*NC,256,(CHK*MP + CHK*DH)*4>>>();
    dim3 gsc(35, BH);
    scan_par<<<gsc,256>>>();
    out_chunk_mma<<<BH*NC,256,OC_SMEM>>>();

    half_copy<<<(DM*DM/4+255)/256, 256>>>(Wo, wh3, DM*DM/4);
    dim3 go(DM/128, ROWS/128);
    hgemm_out<<<go,256>>>(out, bo);
}

// round 8
// speedup vs baseline: 6.8815x; 1.6542x over previous
#include <cuda_runtime.h>
#include <cuda_fp16.h>
#include <math.h>

#define BSZ 2
#define HEADS 16
#define SEQ 4096
#define DH 64
#define DM 1024
#define MF 266
#define MPX 288          // padded feature dim (pad entries exact zeros)
#define CHK 128
#define NC 32
#define BH 32
#define TOK (BH*SEQ)
#define ROWS (BSZ*SEQ)

#define NORMALIZER 0.35355339059327373f
#define DIAG_COEF 0.0625f
#define RATIO 0.061313933948496584f
#define KEPS 1e-4f
#define CEPS 1e-6f
#define KSCALE 256.0f    // k' scale for fp16 range; cancels in O = N/D

// ---------------- static scratch ----------------
__device__ __half g_qh[(size_t)TOK*DH];
__device__ __half g_kh[(size_t)TOK*DH];
__device__ __half g_vh[(size_t)TOK*DH];
__device__ __half g_qp[(size_t)TOK*MPX];
__device__ __half g_kp[(size_t)TOK*MPX];
__device__ __half g_csh[(size_t)BH*NC*MPX*DH];
__device__ __half g_zsh[(size_t)BH*NC*MPX];
__device__ __half g_attn[(size_t)ROWS*DM];
__device__ __half g_projh[384*DH];
__device__ __half g_xh[(size_t)ROWS*DM];
__device__ __half g_wh3[(size_t)3*DM*DM];
__device__ unsigned int g_kmax_bits;

__device__ __forceinline__ unsigned int enc_f(float f){
    unsigned int u = __float_as_uint(f);
    return (u & 0x80000000u) ? ~u : (u | 0x80000000u);
}
__device__ __forceinline__ float dec_f(unsigned int u){
    return (u & 0x80000000u) ? __uint_as_float(u & 0x7fffffffu)
                             : __uint_as_float(~u);
}
__device__ __forceinline__ unsigned sptr(const void* p){
    return (unsigned)__cvta_generic_to_shared(p);
}
#define CP16(dst,src) asm volatile("cp.async.cg.shared.global [%0], [%1], 16;"::"r"(dst),"l"(src))
#define CPCOMMIT() asm volatile("cp.async.commit_group;")
#define CPWAIT1() asm volatile("cp.async.wait_group 1;")
#define CPWAIT0() asm volatile("cp.async.wait_group 0;")
#define LDM4(r0,r1,r2,r3,addr) \
    asm volatile("ldmatrix.sync.aligned.m8n8.x4.shared.b16 {%0,%1,%2,%3}, [%4];" \
        :"=r"(r0),"=r"(r1),"=r"(r2),"=r"(r3):"r"(addr))
#define LDM4T(r0,r1,r2,r3,addr) \
    asm volatile("ldmatrix.sync.aligned.m8n8.x4.trans.shared.b16 {%0,%1,%2,%3}, [%4];" \
        :"=r"(r0),"=r"(r1),"=r"(r2),"=r"(r3):"r"(addr))
#define LDM2T(r0,r1,addr) \
    asm volatile("ldmatrix.sync.aligned.m8n8.x2.trans.shared.b16 {%0,%1}, [%2];" \
        :"=r"(r0),"=r"(r1):"r"(addr))
#define MMA16(acc,a0,a1,a2,a3,b0,b1) \
    asm volatile("mma.sync.aligned.m16n8k16.row.col.f32.f16.f16.f32 " \
        "{%0,%1,%2,%3},{%4,%5,%6,%7},{%8,%9},{%0,%1,%2,%3};" \
        :"+f"(acc[0]),"+f"(acc[1]),"+f"(acc[2]),"+f"(acc[3]) \
        :"r"(a0),"r"(a1),"r"(a2),"r"(a3),"r"(b0),"r"(b1))

// ================= fp16 GEMM core: C[128,128] = A[128,K]h * B[128,K]h^T =====
#define H_ISSUE(t,Abase,Bbase,Ksz) { int s_=(t)%3; \
    __half* As_=smh+s_*8192; __half* Bs_=As_+4096; \
    const __half* Ag_=(Abase)+(size_t)(t)*32; \
    const __half* Bg_=(Bbase)+(size_t)(t)*32; \
    _Pragma("unroll") for(int h=0;h<2;h++){ \
      int id=tid+h*256; int row=id>>2, cc=id&3; \
      unsigned sw=(unsigned)((cc^((row>>1)&3))*16); \
      CP16(sptr((char*)As_+row*64+sw), Ag_+(size_t)row*(Ksz)+cc*8); \
      CP16(sptr((char*)Bs_+row*64+sw), Bg_+(size_t)row*(Ksz)+cc*8); } \
    CPCOMMIT(); }

#define HGEMM_CORE(Abase,Bbase,Ksz,kt) \
    H_ISSUE(0,Abase,Bbase,Ksz); \
    if ((kt)>1) H_ISSUE(1,Abase,Bbase,Ksz); \
    for (int t=0;t<(kt);t++){ \
        if (t+1<(kt)) CPWAIT1(); else CPWAIT0(); \
        __syncthreads(); \
        __half* As = smh + (t%3)*8192; \
        __half* Bs = As + 4096; \
        _Pragma("unroll") \
        for (int k16=0;k16<2;k16++){ \
            unsigned a[4][4]; \
            _Pragma("unroll") \
            for (int mf=0;mf<4;mf++){ \
                int row = wm + mf*16 + lrow; \
                int qd = 2*k16 + lco; \
                unsigned ad = sptr((char*)As + row*64 + ((qd^((row>>1)&3))*16)); \
                LDM4(a[mf][0],a[mf][1],a[mf][2],a[mf][3],ad); \
            } \
            unsigned b[4][2]; \
            _Pragma("unroll") \
            for (int p=0;p<2;p++){ \
                int row = wn + p*16 + lrow; \
                int qd = 2*k16 + lco; \
                unsigned ad = sptr((char*)Bs + row*64 + ((qd^((row>>1)&3))*16)); \
                unsigned r0,r1,r2,r3; LDM4(r0,r1,r2,r3,ad); \
                b[2*p][0]=r0; b[2*p+1][0]=r1; b[2*p][1]=r2; b[2*p+1][1]=r3; \
            } \
            _Pragma("unroll") \
            for (int mf=0;mf<4;mf++) \
                _Pragma("unroll") \
                for (int nf=0;nf<4;nf++) \
                    MMA16(acc[mf][nf],a[mf][0],a[mf][1],a[mf][2],a[mf][3], \
                          b[nf][0],b[nf][1]); \
        } \
        __syncthreads(); \
        if (t+2<(kt)) H_ISSUE(t+2,Abase,Bbase,Ksz); \
    }

#define GEMM_PREAMBLE() \
    const int tid=threadIdx.x, lane=tid&31, wid=tid>>5; \
    const int wm=(wid&1)*64, wn=(wid>>1)*32; \
    const int qr=lane>>2, qc=lane&3; \
    const int lrow=(lane&7)+(lane&8); \
    const int lco=lane>>4; \
    float acc[4][4][4]; \
    _Pragma("unroll") \
    for(int i=0;i<4;i++) \
        _Pragma("unroll") \
        for(int j=0;j<4;j++){acc[i][j][0]=0;acc[i][j][1]=0;acc[i][j][2]=0;acc[i][j][3]=0;}

// ---------------- fused QKV GEMM (fp16 in, fp16 split-head out) -------------
__global__ __launch_bounds__(256,2)
void hgemm_qkv(const float* __restrict__ bq, const float* __restrict__ bk,
               const float* __restrict__ bv)
{
    __shared__ __half smh[3*8192];
    const int m0=blockIdx.y*128, n0=blockIdx.x*128;
    GEMM_PREAMBLE();
    const __half* Abase = g_xh  + (size_t)m0*DM;
    const __half* Bbase = g_wh3 + (size_t)n0*DM;
    HGEMM_CORE(Abase, Bbase, DM, 32);

    #pragma unroll
    for (int mf=0;mf<4;mf++){
        int tr0 = m0 + wm + mf*16 + qr;
        int b0 = tr0 >> 12, n_ = tr0 & 4095;
        #pragma unroll
        for (int nf=0;nf<4;nf++){
            int col = n0 + wn + nf*8 + qc*2;
            int sel = col >> 10;
            int c1  = col & 1023;
            int h = c1 >> 6, d = c1 & 63;
            const float* bias = (sel==0) ? bq : (sel==1) ? bk : bv;
            __half* dst = (sel==0) ? g_qh : (sel==1) ? g_kh : g_vh;
            float bb0 = bias[c1], bb1 = bias[c1+1];
            size_t base0 = (((size_t)(b0*HEADS+h))*SEQ + n_)*DH + d;
            size_t base1 = (((size_t)(b0*HEADS+h))*SEQ + n_ + 8)*DH + d;
            *(__half2*)(dst + base0) = __floats2half2_rn(acc[mf][nf][0]+bb0, acc[mf][nf][1]+bb1);
            *(__half2*)(dst + base1) = __floats2half2_rn(acc[mf][nf][2]+bb0, acc[mf][nf][3]+bb1);
        }
    }
}

// ---------------- output projection GEMM (fp16 in, fp32 out) -----------------
__global__ __launch_bounds__(256,2)
void hgemm_out(float* __restrict__ C, const float* __restrict__ bias)
{
    __shared__ __half smh[3*8192];
    const int m0=blockIdx.y*128, n0=blockIdx.x*128;
    GEMM_PREAMBLE();
    const __half* Abase = g_attn + (size_t)m0*DM;
    const __half* Bbase = g_wh3  + (size_t)n0*DM;
    HGEMM_CORE(Abase, Bbase, DM, 32);

    #pragma unroll
    for (int mf=0;mf<4;mf++){
        #pragma unroll
        for (int nf=0;nf<4;nf++){
            int row = m0 + wm + mf*16 + qr;
            int col = n0 + wn + nf*8 + qc*2;
            float b0 = bias[col], b1 = bias[col+1];
            float2 v0; v0.x=acc[mf][nf][0]+b0; v0.y=acc[mf][nf][1]+b1;
            float2 v1; v1.x=acc[mf][nf][2]+b0; v1.y=acc[mf][nf][3]+b1;
            *(float2*)(C + (size_t)row*DM + col)     = v0;
            *(float2*)(C + (size_t)(row+8)*DM + col) = v1;
        }
    }
}

// ---------------- feature GEMM fp16 (z=0: q, z=1: k + fused global max) -----
__global__ __launch_bounds__(256,2)
void hgemm_feat()
{
    __shared__ __half smh[3*8192];
    const int z = blockIdx.z;
    const __half* A = z ? g_kh : g_qh;
    __half* C = z ? g_kp : g_qp;
    const int m0=blockIdx.y*128, n0=blockIdx.x*128;
    GEMM_PREAMBLE();
    const __half* Abase = A + (size_t)m0*DH;
    const __half* Bbase = g_projh + (size_t)n0*DH;
    HGEMM_CORE(Abase, Bbase, DH, 2);

    float mx = -3.4e38f;
    #pragma unroll
    for (int mf=0;mf<4;mf++){
        int row = m0 + wm + mf*16 + qr;
        #pragma unroll
        for (int nf=0;nf<4;nf++){
            int col = n0 + wn + nf*8 + qc*2;
            if (col < MPX){
                *(__half2*)(C + (size_t)row*MPX + col)     = __floats2half2_rn(acc[mf][nf][0], acc[mf][nf][1]);
                *(__half2*)(C + (size_t)(row+8)*MPX + col) = __floats2half2_rn(acc[mf][nf][2], acc[mf][nf][3]);
                if (z){
                    if (col   < MF){ mx = fmaxf(mx, acc[mf][nf][0]); mx = fmaxf(mx, acc[mf][nf][2]); }
                    if (col+1 < MF){ mx = fmaxf(mx, acc[mf][nf][1]); mx = fmaxf(mx, acc[mf][nf][3]); }
                }
            }
        }
    }
    if (z){
        #pragma unroll
        for (int o=16;o;o>>=1) mx = fmaxf(mx, __shfl_xor_sync(0xffffffffu, mx, o));
        __syncthreads();
        float* smf = (float*)smh;
        if (lane==0) smf[wid] = mx;
        __syncthreads();
        if (tid==0){
            float m = smf[0];
            #pragma unroll
            for (int w=1;w<8;w++) m = fmaxf(m, smf[w]);
            atomicMax(&g_kmax_bits, enc_f(m));
        }
    }
}

// ---------------- prep ----------------
__global__ void prep_kernel(const float* __restrict__ proj){
    int idx = blockIdx.x*256 + threadIdx.x;
    if (idx == 0) g_kmax_bits = 0u;
    if (idx < 384*DH){
        int m = idx / DH, d = idx % DH;
        g_projh[idx] = (m < MF) ? __float2half(proj[m*DH + d] * NORMALIZER) : __float2half(0.f);
    }
}

__global__ void half_copy(const float* __restrict__ s, __half* __restrict__ d, int n4){
    int i = blockIdx.x*256 + threadIdx.x;
    if (i < n4){
        float4 v = ((const float4*)s)[i];
        ((__half2*)d)[i*2]   = __floats2half2_rn(v.x, v.y);
        ((__half2*)d)[i*2+1] = __floats2half2_rn(v.z, v.w);
    }
}

// ---------------- exp feature map in-place (fp16) -----------------------------
__global__ void feat_apply(const __half* __restrict__ data,
                           __half* __restrict__ ddb, int is_query)
{
    int warp = threadIdx.x >> 5, lane = threadIdx.x & 31;
    size_t row = (size_t)blockIdx.x*8 + warp;
    float2 qq = __half22float2(((const __half2*)(data + row*DH))[lane]);
    float s = qq.x*qq.x + qq.y*qq.y;
    #pragma unroll
    for (int o=16;o;o>>=1) s += __shfl_xor_sync(0xffffffffu, s, o);
    float diag = DIAG_COEF * s;

    __half* dd = ddb + row*MPX;
    float vals[9];
    float mx;
    const float scale = is_query ? RATIO : (KSCALE*RATIO);
    if (is_query){
        mx = -3.4e38f;
        #pragma unroll
        for (int i=0;i<9;i++){
            int m = i*32 + lane;
            float v = __half2float(dd[m]);
            vals[i] = v;
            if (m < MF) mx = fmaxf(mx, v);
        }
        #pragma unroll
        for (int o=16;o;o>>=1) mx = fmaxf(mx, __shfl_xor_sync(0xffffffffu, mx, o));
    } else {
        #pragma unroll
        for (int i=0;i<9;i++){
            int m = i*32 + lane;
            vals[i] = __half2float(dd[m]);
        }
        mx = dec_f(g_kmax_bits);
    }
    #pragma unroll
    for (int i=0;i<9;i++){
        int m = i*32 + lane;
        dd[m] = (m < MF) ? __float2half(scale*(expf(vals[i]-diag-mx)+KEPS))
                         : __float2half(0.f);
    }
}

// ---------------- chunk sums via fp16 MMA: Csum[288,64]=K'^T V, zsum --------
// smem: Kt [128][296] fp16, Vt [128][72] fp16 (col64 = ones).
#define CS_SMEM ((128*296 + 128*72)*2)
extern __shared__ __half sh_dyn[];
__global__ __launch_bounds__(256)
void chunk_sums_mma()
{
    __half* Kt = sh_dyn;               // row stride 296
    __half* Vt = sh_dyn + 128*296;     // row stride 72
    const int tid=threadIdx.x, lane=tid&31, wid=tid>>5;
    const int blk=blockIdx.x;
    const size_t tok0=(size_t)blk*CHK;
    const int qr=lane>>2, qc=lane&3;

    #pragma unroll
    for (int j=0;j<18;j++){
        int cid = tid + j*256; int row = cid/36, c = cid%36;
        CP16(sptr(Kt + row*296 + c*8), g_kp + (tok0+row)*MPX + c*8);
    }
    #pragma unroll
    for (int j=0;j<4;j++){
        int cid = tid + j*256; int row = cid>>3, c = cid&7;
        CP16(sptr(Vt + row*72 + c*8), g_vh + (tok0+row)*DH + c*8);
    }
    CPCOMMIT(); CPWAIT0();
    __syncthreads();
    if (tid < 128){
        __half* vr = Vt + tid*72;
        vr[64] = __float2half(1.f);
        #pragma unroll
        for (int j=65;j<72;j++) vr[j] = __float2half(0.f);
    }
    __syncthreads();

    const int nfr = (wid<2) ? 3 : 2;
    int mfs[3]; mfs[0]=wid; mfs[1]=wid+8; mfs[2]=16+wid;
    float acc[3][9][4];
    #pragma unroll
    for(int i=0;i<3;i++)
        #pragma unroll
        for(int j=0;j<9;j++){acc[i][j][0]=0;acc[i][j][1]=0;acc[i][j][2]=0;acc[i][j][3]=0;}

    for (int ks=0;ks<8;ks++){
        int k0 = ks*16;
        int trow = k0 + (lane&7) + ((lane&16)>>1);
        unsigned bf[9][2];
        #pragma unroll
        for (int bi=0;bi<4;bi++){
            unsigned ad = sptr(Vt + trow*72 + bi*16 + (lane&8));
            unsigned r0,r1,r2,r3; LDM4T(r0,r1,r2,r3,ad);
            bf[2*bi][0]=r0; bf[2*bi][1]=r2; bf[2*bi+1][0]=r1; bf[2*bi+1][1]=r3;
        }
        {
            unsigned ad = sptr(Vt + (k0 + (lane&15))*72 + 64);
            unsigned r0,r1; LDM2T(r0,r1,ad);
            bf[8][0]=r0; bf[8][1]=r1;
        }
        for (int fi=0; fi<nfr; fi++){
            unsigned ad = sptr(Kt + trow*296 + mfs[fi]*16 + (lane&8));
            unsigned a0,a1,a2,a3; LDM4T(a0,a1,a2,a3,ad);
            #pragma unroll
            for (int nf=0;nf<9;nf++)
                MMA16(acc[fi][nf], a0,a1,a2,a3, bf[nf][0], bf[nf][1]);
        }
    }

    for (int fi=0; fi<nfr; fi++){
        int m0 = mfs[fi]*16;
        #pragma unroll
        for (int nf=0;nf<8;nf++){
            int col = nf*8 + qc*2;
            *(__half2*)(g_csh + ((size_t)blk*MPX + m0+qr)*DH + col)   = __floats2half2_rn(acc[fi][nf][0], acc[fi][nf][1]);
            *(__half2*)(g_csh + ((size_t)blk*MPX + m0+qr+8)*DH + col) = __floats2half2_rn(acc[fi][nf][2], acc[fi][nf][3]);
        }
        if (qc==0){
            g_zsh[(size_t)blk*MPX + m0+qr]   = __float2half(acc[fi][8][0]);
            g_zsh[(size_t)blk*MPX + m0+qr+8] = __float2half(acc[fi][8][2]);
        }
    }
}

// ---------------- parallel exclusive scan over chunks (fp16, fp32 carry) ----
__global__ __launch_bounds__(256)
void scan_par()
{
    int bh = blockIdx.y;
    if (blockIdx.x < 36){
        int l = blockIdx.x*256 + threadIdx.x;             // [0, 9216)
        __half2* base = (__half2*)(g_csh + (size_t)bh*NC*MPX*DH) + l;
        const int stride = MPX*DH/2;                       // 9216
        float sx=0.f, sy=0.f;
        #pragma unroll
        for (int c=0;c<NC;c++){
            float2 t = __half22float2(base[(size_t)c*stride]);
            base[(size_t)c*stride] = __floats2half2_rn(sx, sy);
            sx += t.x; sy += t.y;
        }
    } else {
        if (threadIdx.x < 144){
            __half2* base = (__half2*)(g_zsh + (size_t)bh*NC*MPX) + threadIdx.x;
            const int stride = MPX/2;                      // 144
            float sx=0.f, sy=0.f;
            #pragma unroll
            for (int c=0;c<NC;c++){
                float2 t = __half22float2(base[(size_t)c*stride]);
                base[(size_t)c*stride] = __floats2half2_rn(sx, sy);
                sx += t.x; sy += t.y;
            }
        }
    }
}

// ---------------- out_chunk via fp16 MMA --------------------------------------
// smem (halfs): stage s at s*10496: Q[128][32], K[128][32], St[32][72];
// Am [128][136] @0 (overlaps stages); Vt [128][72] @20992.
#define OC_STAGE 10496
#define OC_VT 20992
#define OC_SMEM ((20992 + 128*72)*2)
__global__ __launch_bounds__(256)
void out_chunk_h()
{
    __half* Am = sh_dyn;               // row stride 136
    __half* Vt = sh_dyn + OC_VT;       // row stride 72
    const int tid=threadIdx.x, lane=tid&31, wid=tid>>5;
    const int blk=blockIdx.x, bh=blk>>5, c=blk&31;
    const size_t tok0=(size_t)blk*CHK;
    const int qr=lane>>2, qc=lane&3;
    const int lrow=(lane&7)+(lane&8);
    const int lco=lane>>4;
    const __half ceps_h = __float2half(KSCALE*CEPS);

    // Vt loads (complete with first stage wait)
    #pragma unroll
    for (int j=0;j<4;j++){
        int cid = tid + j*256; int row = cid>>3, cc = cid&7;
        CP16(sptr(Vt + row*72 + cc*8), g_vh + (tok0+row)*DH + cc*8);
    }

    float accA[16][4];
    float accO[9][4];
    #pragma unroll
    for(int i=0;i<16;i++){accA[i][0]=0;accA[i][1]=0;accA[i][2]=0;accA[i][3]=0;}
    #pragma unroll
    for(int i=0;i<9;i++){accO[i][0]=0;accO[i][1]=0;accO[i][2]=0;accO[i][3]=0;}

#define OCH_ISSUE(t) { int s_=(t)&1; \
    __half* Qs_=sh_dyn+s_*OC_STAGE; __half* Ks_=Qs_+4096; __half* Ss_=Qs_+8192; \
    _Pragma("unroll") for(int h=0;h<2;h++){ \
      int id=tid+h*256; int row=id>>2, cc=id&3; \
      unsigned sw=(unsigned)((cc^((row>>1)&3))*16); \
      CP16(sptr((char*)Qs_+row*64+sw), g_qp+(tok0+row)*MPX+(t)*32+cc*8); \
      CP16(sptr((char*)Ks_+row*64+sw), g_kp+(tok0+row)*MPX+(t)*32+cc*8); } \
    { int row=tid>>3, cc=tid&7; \
      CP16(sptr(Ss_+row*72+cc*8), g_csh+((size_t)blk*MPX+(t)*32+row)*DH+cc*8); } \
    if (tid<32){ __half* sr=Ss_+tid*72; sr[64]=g_zsh[(size_t)blk*MPX+(t)*32+tid]; \
      sr[65]=ceps_h; \
      _Pragma("unroll") for(int j=66;j<72;j++) sr[j]=__float2half(0.f); } \
    CPCOMMIT(); }

    OCH_ISSUE(0);
    for (int t=0;t<9;t++){
        if (t+1<9) OCH_ISSUE(t+1);
        if (t<8) CPWAIT1(); else CPWAIT0();
        __syncthreads();
        __half* Qs = sh_dyn + (t&1)*OC_STAGE;
        __half* Ks = Qs + 4096;
        __half* Ss = Qs + 8192;
        #pragma unroll
        for (int k16=0;k16<2;k16++){
            unsigned a[4];
            {
                int row = wid*16 + lrow;
                int qd = 2*k16 + lco;
                unsigned ad = sptr((char*)Qs + row*64 + ((qd^((row>>1)&3))*16));
                LDM4(a[0],a[1],a[2],a[3],ad);
            }
            #pragma unroll
            for (int p=0;p<8;p++){
                int row = p*16 + lrow;
                int qd = 2*k16 + lco;
                unsigned ad = sptr((char*)Ks + row*64 + ((qd^((row>>1)&3))*16));
                unsigned r0,r1,r2,r3; LDM4(r0,r1,r2,r3,ad);
                MMA16(accA[2*p],  a[0],a[1],a[2],a[3], r0, r2);
                MMA16(accA[2*p+1],a[0],a[1],a[2],a[3], r1, r3);
            }
            {
                int trow = k16*16 + (lane&7) + ((lane&16)>>1);
                unsigned bf[9][2];
                #pragma unroll
                for (int bi=0;bi<4;bi++){
                    unsigned ad = sptr(Ss + trow*72 + bi*16 + (lane&8));
                    unsigned r0,r1,r2,r3; LDM4T(r0,r1,r2,r3,ad);
                    bf[2*bi][0]=r0; bf[2*bi][1]=r2; bf[2*bi+1][0]=r1; bf[2*bi+1][1]=r3;
                }
                {
                    unsigned ad = sptr(Ss + (k16*16 + (lane&15))*72 + 64);
                    unsigned r0,r1; LDM2T(r0,r1,ad);
                    bf[8][0]=r0; bf[8][1]=r1;
                }
                #pragma unroll
                for (int nf=0;nf<9;nf++)
                    MMA16(accO[nf], a[0],a[1],a[2],a[3], bf[nf][0], bf[nf][1]);
            }
        }
        __syncthreads();
    }

    // Vt ones column (Vt loaded long ago)
    if (tid < 128){
        __half* vr = Vt + tid*72;
        vr[64] = __float2half(1.f);
        #pragma unroll
        for (int j=65;j<72;j++) vr[j] = __float2half(0.f);
    }
    // masked A -> Am (fp16)
    #pragma unroll
    for (int nf=0;nf<16;nf++){
        int col = nf*8 + qc*2;
        int r0 = wid*16 + qr, r1 = r0 + 8;
        *(__half2*)(Am + r0*136 + col) = __floats2half2_rn(
            (col <= r0) ? accA[nf][0] : 0.f, (col+1 <= r0) ? accA[nf][1] : 0.f);
        *(__half2*)(Am + r1*136 + col) = __floats2half2_rn(
            (col <= r1) ? accA[nf][2] : 0.f, (col+1 <= r1) ? accA[nf][3] : 0.f);
    }
    __syncthreads();

    // phase 2: accO += maskedA @ Vt  (k = 128 tokens)
    for (int kt=0;kt<8;kt++){
        unsigned a[4];
        {
            int row = wid*16 + lrow;
            unsigned ad = sptr((char*)Am + row*272 + kt*32 + lco*16);
            LDM4(a[0],a[1],a[2],a[3],ad);
        }
        int trow = kt*16 + (lane&7) + ((lane&16)>>1);
        unsigned bf[9][2];
        #pragma unroll
        for (int bi=0;bi<4;bi++){
            unsigned ad = sptr(Vt + trow*72 + bi*16 + (lane&8));
            unsigned r0,r1,r2,r3; LDM4T(r0,r1,r2,r3,ad);
            bf[2*bi][0]=r0; bf[2*bi][1]=r2; bf[2*bi+1][0]=r1; bf[2*bi+1][1]=r3;
        }
        {
            unsigned ad = sptr(Vt + (kt*16 + (lane&15))*72 + 64);
            unsigned r0,r1; LDM2T(r0,r1,ad);
            bf[8][0]=r0; bf[8][1]=r1;
        }
        #pragma unroll
        for (int nf=0;nf<9;nf++)
            MMA16(accO[nf], a[0],a[1],a[2],a[3], bf[nf][0], bf[nf][1]);
    }

    // denominators: col64 (z + rowsum) + col65 (KSCALE*CEPS*sum_q)
    float d0 = accO[8][0] + accO[8][1];
    float d1 = accO[8][2] + accO[8][3];
    d0 = __shfl_sync(0xffffffffu, d0, lane & ~3);
    d1 = __shfl_sync(0xffffffffu, d1, lane & ~3);
    float inv0 = 1.f/d0, inv1 = 1.f/d1;

    int b = bh >> 4, h = bh & 15;
    int n0 = c*CHK + wid*16;
    #pragma unroll
    for (int nf=0;nf<8;nf++){
        int col = h*64 + nf*8 + qc*2;
        __half2* o0 = (__half2*)(g_attn + ((size_t)(b*SEQ + n0 + qr))*DM + col);
        __half2* o1 = (__half2*)(g_attn + ((size_t)(b*SEQ + n0 + qr + 8))*DM + col);
        *o0 = __floats2half2_rn(accO[nf][0]*inv0, accO[nf][1]*inv0);
        *o1 = __floats2half2_rn(accO[nf][2]*inv1, accO[nf][3]*inv1);
    }
#undef OCH_ISSUE
}

// ---------------- launch ------------------------------------------------------
extern "C" void kernel_launch(void* const* d_in, const int* in_sizes, int n_in,
                              void* d_out, int out_size)
{
    (void)in_sizes; (void)n_in; (void)out_size;
    const float* x    = (const float*)d_in[0];
    const float* Wq   = (const float*)d_in[1];
    const float* bq   = (const float*)d_in[2];
    const float* Wk   = (const float*)d_in[3];
    const float* bk   = (const float*)d_in[4];
    const float* Wv   = (const float*)d_in[5];
    const float* bv   = (const float*)d_in[6];
    const float* Wo   = (const float*)d_in[7];
    const float* bo   = (const float*)d_in[8];
    const float* proj = (const float*)d_in[9];
    float* out = (float*)d_out;

    cudaFuncSetAttribute(chunk_sums_mma, cudaFuncAttributeMaxDynamicSharedMemorySize, CS_SMEM);
    cudaFuncSetAttribute(out_chunk_h, cudaFuncAttributeMaxDynamicSharedMemorySize, OC_SMEM);

    __half *xh,*wh3,*qh,*kh,*qp,*kp;
    cudaGetSymbolAddress((void**)&xh,  g_xh);
    cudaGetSymbolAddress((void**)&wh3, g_wh3);
    cudaGetSymbolAddress((void**)&qh,  g_qh);
    cudaGetSymbolAddress((void**)&kh,  g_kh);
    cudaGetSymbolAddress((void**)&qp,  g_qp);
    cudaGetSymbolAddress((void**)&kp,  g_kp);

    prep_kernel<<<(384*DH+255)/256, 256>>>(proj);
    half_copy<<<(ROWS*DM/4+255)/256, 256>>>(x, xh, ROWS*DM/4);
    half_copy<<<(DM*DM/4+255)/256, 256>>>(Wq, wh3,           DM*DM/4);
    half_copy<<<(DM*DM/4+255)/256, 256>>>(Wk, wh3 +   DM*DM, DM*DM/4);
    half_copy<<<(DM*DM/4+255)/256, 256>>>(Wv, wh3 + 2*DM*DM, DM*DM/4);

    dim3 gq(3*DM/128, ROWS/128);   // (24, 64)
    hgemm_qkv<<<gq,256>>>(bq, bk, bv);

    dim3 gf(3, TOK/128, 2);
    hgemm_feat<<<gf,256>>>();

    feat_apply<<<TOK/8,256>>>(qh, qp, 1);
    feat_apply<<<TOK/8,256>>>(kh, kp, 0);

    chunk_sums_mma<<<BH*NC,256,CS_SMEM>>>();
    dim3 gsc(37, BH);
    scan_par<<<gsc,256>>>();
    out_chunk_h<<<BH*NC,256,OC_SMEM>>>();

    half_copy<<<(DM*DM/4+255)/256, 256>>>(Wo, wh3, DM*DM/4);
    dim3 go(DM/128, ROWS/128);
    hgemm_out<<<go,256>>>(out, bo);
}